// round 1
// baseline (speedup 1.0000x reference)
#include <cuda_runtime.h>
#include <cuda_bf16.h>
#include <math.h>
#include <math_constants.h>

// Problem constants
#define B_   2
#define S_   2048
#define HID_ 2048
#define NH_  16
#define NKV_ 4
#define HD_  128
#define ROWS_ (B_ * S_)          // 4096

// ---------------- scratch (device globals; no allocation allowed) ----------
__device__ float g_q[ROWS_ * NH_ * HD_];     // 4096 x 2048
__device__ float g_k[ROWS_ * NKV_ * HD_];    // 4096 x 512
__device__ float g_v[ROWS_ * NKV_ * HD_];    // 4096 x 512
__device__ float g_attn[ROWS_ * NH_ * HD_];  // 4096 x 2048
__device__ float g_cos[S_ * (HD_ / 2)];      // 2048 x 64
__device__ float g_sin[S_ * (HD_ / 2)];

// ---------------- RoPE cos/sin table (double precision angles) -------------
__global__ void rope_table_kernel(float* cs, float* sn) {
    int idx = blockIdx.x * blockDim.x + threadIdx.x;
    if (idx >= S_ * (HD_ / 2)) return;
    int s = idx >> 6;          // / 64
    int p = idx & 63;          // % 64
    double freq = exp(-((double)(2 * p) / (double)HD_) * log(10000.0));
    double ang = (double)s * freq;
    double sv, cv;
    sincos(ang, &sv, &cv);
    cs[idx] = (float)cv;
    sn[idx] = (float)sv;
}

// ---------------- RoPE apply (in place) -------------------------------------
__global__ void rope_apply_kernel(float* x, const float* __restrict__ cs,
                                  const float* __restrict__ sn, int heads) {
    int idx = blockIdx.x * blockDim.x + threadIdx.x;
    int total = ROWS_ * heads * (HD_ / 2);
    if (idx >= total) return;
    int p = idx & 63;
    int h = (idx >> 6) % heads;
    int row = idx / (64 * heads);
    int s = row & (S_ - 1);
    float c = cs[s * 64 + p];
    float sv = sn[s * 64 + p];
    float2* base = (float2*)(x + (size_t)row * heads * HD_ + h * HD_ + 2 * p);
    float2 v = *base;
    float2 o;
    o.x = v.x * c - v.y * sv;
    o.y = v.x * sv + v.y * c;
    *base = o;
}

// ---------------- SGEMM: C[M,N] = A[M,K] @ B[K,N] (+bias) ------------------
// BM=128 BN=128 BK=16, 256 threads, 8x8 per thread.
#define GBM 128
#define GBN 128
#define GBK 16
#define APAD 132   // padded leading dim for As

__global__ __launch_bounds__(256) void sgemm_bias_kernel(
    const float* __restrict__ A, const float* __restrict__ Bm,
    const float* __restrict__ bias, float* __restrict__ C,
    int M, int N, int K) {
    __shared__ float As[GBK][APAD];
    __shared__ float Bs[GBK][GBN];

    int tid = threadIdx.x;
    int block_row = blockIdx.y * GBM;
    int block_col = blockIdx.x * GBN;
    int tr = (tid >> 4) * 8;   // row offset within tile
    int tc = (tid & 15) * 8;   // col offset within tile

    float acc[8][8];
#pragma unroll
    for (int i = 0; i < 8; i++)
#pragma unroll
        for (int j = 0; j < 8; j++) acc[i][j] = 0.0f;

    for (int k0 = 0; k0 < K; k0 += GBK) {
        // load A tile (128 x 16), store transposed
#pragma unroll
        for (int i = 0; i < 2; i++) {
            int idx = tid + i * 256;
            int r = idx >> 2;            // 0..127
            int c4 = (idx & 3) * 4;      // 0,4,8,12
            float4 v = *(const float4*)&A[(size_t)(block_row + r) * K + k0 + c4];
            As[c4 + 0][r] = v.x;
            As[c4 + 1][r] = v.y;
            As[c4 + 2][r] = v.z;
            As[c4 + 3][r] = v.w;
        }
        // load B tile (16 x 128)
#pragma unroll
        for (int i = 0; i < 2; i++) {
            int idx = tid + i * 256;
            int r = idx >> 5;            // 0..15
            int c4 = (idx & 31) * 4;
            *(float4*)&Bs[r][c4] = *(const float4*)&Bm[(size_t)(k0 + r) * N + block_col + c4];
        }
        __syncthreads();

#pragma unroll
        for (int k = 0; k < GBK; k++) {
            float a[8], b[8];
            float4 a0 = *(const float4*)&As[k][tr];
            float4 a1 = *(const float4*)&As[k][tr + 4];
            a[0] = a0.x; a[1] = a0.y; a[2] = a0.z; a[3] = a0.w;
            a[4] = a1.x; a[5] = a1.y; a[6] = a1.z; a[7] = a1.w;
            float4 b0 = *(const float4*)&Bs[k][tc];
            float4 b1 = *(const float4*)&Bs[k][tc + 4];
            b[0] = b0.x; b[1] = b0.y; b[2] = b0.z; b[3] = b0.w;
            b[4] = b1.x; b[5] = b1.y; b[6] = b1.z; b[7] = b1.w;
#pragma unroll
            for (int i = 0; i < 8; i++)
#pragma unroll
                for (int j = 0; j < 8; j++) acc[i][j] = fmaf(a[i], b[j], acc[i][j]);
        }
        __syncthreads();
    }

    // epilogue
#pragma unroll
    for (int i = 0; i < 8; i++) {
        int gr = block_row + tr + i;
#pragma unroll
        for (int j = 0; j < 8; j += 4) {
            int gc = block_col + tc + j;
            float4 v;
            v.x = acc[i][j + 0];
            v.y = acc[i][j + 1];
            v.z = acc[i][j + 2];
            v.w = acc[i][j + 3];
            if (bias) {
                v.x += bias[gc + 0];
                v.y += bias[gc + 1];
                v.z += bias[gc + 2];
                v.w += bias[gc + 3];
            }
            *(float4*)&C[(size_t)gr * N + gc] = v;
        }
    }
}

// ---------------- Flash attention (fp32, causal, GQA) ----------------------
// Tiles: 64 q-rows x 64 kv-rows, HD=128. 256 threads.
// S-phase thread map: (r=tid/16, c=tid%16) -> s[4][4] at rows 4r.., cols 4c..
// PV-phase map:       (r, c) -> acc[4][8] at rows 4r.., cols 8c..
#define FPAD 68  // padded leading dim for transposed Q/K and for P

#define SM_QS 0
#define SM_KS (128 * FPAD)
#define SM_VS (SM_KS + 128 * FPAD)
#define SM_PS (SM_VS + 64 * 128)
#define FLASH_SMEM_FLOATS (SM_PS + 64 * FPAD)
#define FLASH_SMEM_BYTES (FLASH_SMEM_FLOATS * 4)

__global__ __launch_bounds__(256) void flash_kernel(
    const float* __restrict__ q, const float* __restrict__ k,
    const float* __restrict__ v, float* __restrict__ o) {
    int qt = blockIdx.x;
    int h = blockIdx.y;
    int b = blockIdx.z;
    int kvh = h >> 2;  // N_HEADS / N_KV = 4

    extern __shared__ float sm[];
    float* Qs = sm + SM_QS;   // [128][FPAD] d-major
    float* Ks = sm + SM_KS;   // [128][FPAD] d-major
    float* Vs = sm + SM_VS;   // [64][128]
    float* Ps = sm + SM_PS;   // [64][FPAD]

    int tid = threadIdx.x;
    int r = tid >> 4;
    int c = tid & 15;
    const float scale = 0.08838834764831845f;  // 1/sqrt(128)

    // Load Q tile transposed (d-major)
    const float* qbase = q + ((size_t)(b * S_ + qt * 64)) * (NH_ * HD_) + h * HD_;
#pragma unroll
    for (int i = 0; i < 8; i++) {
        int idx = tid + i * 256;
        int row = idx >> 5;
        int d4 = (idx & 31) * 4;
        float4 val = *(const float4*)&qbase[(size_t)row * (NH_ * HD_) + d4];
        Qs[(d4 + 0) * FPAD + row] = val.x;
        Qs[(d4 + 1) * FPAD + row] = val.y;
        Qs[(d4 + 2) * FPAD + row] = val.z;
        Qs[(d4 + 3) * FPAD + row] = val.w;
    }

    float m[4], l[4], acc[4][8];
#pragma unroll
    for (int i = 0; i < 4; i++) {
        m[i] = -CUDART_INF_F;
        l[i] = 0.0f;
#pragma unroll
        for (int j = 0; j < 8; j++) acc[i][j] = 0.0f;
    }

    for (int jt = 0; jt <= qt; jt++) {
        __syncthreads();  // protect Ks/Vs from previous iteration readers
        const float* kbase = k + ((size_t)(b * S_ + jt * 64)) * (NKV_ * HD_) + kvh * HD_;
        const float* vbase = v + ((size_t)(b * S_ + jt * 64)) * (NKV_ * HD_) + kvh * HD_;
#pragma unroll
        for (int i = 0; i < 8; i++) {
            int idx = tid + i * 256;
            int row = idx >> 5;
            int d4 = (idx & 31) * 4;
            float4 kv4 = *(const float4*)&kbase[(size_t)row * (NKV_ * HD_) + d4];
            Ks[(d4 + 0) * FPAD + row] = kv4.x;
            Ks[(d4 + 1) * FPAD + row] = kv4.y;
            Ks[(d4 + 2) * FPAD + row] = kv4.z;
            Ks[(d4 + 3) * FPAD + row] = kv4.w;
            *(float4*)&Vs[row * 128 + d4] =
                *(const float4*)&vbase[(size_t)row * (NKV_ * HD_) + d4];
        }
        __syncthreads();

        // S = Q K^T
        float sv[4][4];
#pragma unroll
        for (int i = 0; i < 4; i++)
#pragma unroll
            for (int j = 0; j < 4; j++) sv[i][j] = 0.0f;

#pragma unroll 4
        for (int kk = 0; kk < 128; kk++) {
            float4 qa = *(const float4*)&Qs[kk * FPAD + 4 * r];
            float4 kb = *(const float4*)&Ks[kk * FPAD + 4 * c];
            float aq[4] = {qa.x, qa.y, qa.z, qa.w};
            float bk[4] = {kb.x, kb.y, kb.z, kb.w};
#pragma unroll
            for (int i = 0; i < 4; i++)
#pragma unroll
                for (int j = 0; j < 4; j++) sv[i][j] = fmaf(aq[i], bk[j], sv[i][j]);
        }

        // scale + causal mask (only diagonal tile needs it)
        bool diag = (jt == qt);
#pragma unroll
        for (int i = 0; i < 4; i++)
#pragma unroll
            for (int j = 0; j < 4; j++) {
                float val = sv[i][j] * scale;
                if (diag && (4 * c + j) > (4 * r + i)) val = -CUDART_INF_F;
                sv[i][j] = val;
            }

        // online softmax update
#pragma unroll
        for (int i = 0; i < 4; i++) {
            float rm = fmaxf(fmaxf(sv[i][0], sv[i][1]), fmaxf(sv[i][2], sv[i][3]));
#pragma unroll
            for (int msk = 1; msk < 16; msk <<= 1)
                rm = fmaxf(rm, __shfl_xor_sync(0xffffffff, rm, msk));
            float mn = fmaxf(m[i], rm);
            float alpha = expf(m[i] - mn);
            float p0 = expf(sv[i][0] - mn);
            float p1 = expf(sv[i][1] - mn);
            float p2 = expf(sv[i][2] - mn);
            float p3 = expf(sv[i][3] - mn);
            float rs = p0 + p1 + p2 + p3;
#pragma unroll
            for (int msk = 1; msk < 16; msk <<= 1)
                rs += __shfl_xor_sync(0xffffffff, rs, msk);
            l[i] = l[i] * alpha + rs;
            m[i] = mn;
#pragma unroll
            for (int j = 0; j < 8; j++) acc[i][j] *= alpha;
            Ps[(4 * r + i) * FPAD + 4 * c + 0] = p0;
            Ps[(4 * r + i) * FPAD + 4 * c + 1] = p1;
            Ps[(4 * r + i) * FPAD + 4 * c + 2] = p2;
            Ps[(4 * r + i) * FPAD + 4 * c + 3] = p3;
        }
        __syncthreads();

        // acc += P @ V
#pragma unroll 2
        for (int kk = 0; kk < 64; kk++) {
            float4 va = *(const float4*)&Vs[kk * 128 + 8 * c];
            float4 vb = *(const float4*)&Vs[kk * 128 + 8 * c + 4];
#pragma unroll
            for (int i = 0; i < 4; i++) {
                float pp = Ps[(4 * r + i) * FPAD + kk];
                acc[i][0] = fmaf(pp, va.x, acc[i][0]);
                acc[i][1] = fmaf(pp, va.y, acc[i][1]);
                acc[i][2] = fmaf(pp, va.z, acc[i][2]);
                acc[i][3] = fmaf(pp, va.w, acc[i][3]);
                acc[i][4] = fmaf(pp, vb.x, acc[i][4]);
                acc[i][5] = fmaf(pp, vb.y, acc[i][5]);
                acc[i][6] = fmaf(pp, vb.z, acc[i][6]);
                acc[i][7] = fmaf(pp, vb.w, acc[i][7]);
            }
        }
    }

    // epilogue: normalize, write to attn buffer [B*S, NH*HD]
    float* obase = o + ((size_t)(b * S_ + qt * 64)) * (NH_ * HD_) + h * HD_;
#pragma unroll
    for (int i = 0; i < 4; i++) {
        float inv = 1.0f / l[i];
        int row = 4 * r + i;
        float4 v0, v1;
        v0.x = acc[i][0] * inv; v0.y = acc[i][1] * inv;
        v0.z = acc[i][2] * inv; v0.w = acc[i][3] * inv;
        v1.x = acc[i][4] * inv; v1.y = acc[i][5] * inv;
        v1.z = acc[i][6] * inv; v1.w = acc[i][7] * inv;
        *(float4*)&obase[(size_t)row * (NH_ * HD_) + 8 * c] = v0;
        *(float4*)&obase[(size_t)row * (NH_ * HD_) + 8 * c + 4] = v1;
    }
}

// ---------------- launch ----------------------------------------------------
extern "C" void kernel_launch(void* const* d_in, const int* in_sizes, int n_in,
                              void* d_out, int out_size) {
    const float* hs  = (const float*)d_in[0];
    const float* q_w = (const float*)d_in[1];
    const float* q_b = (const float*)d_in[2];
    const float* k_w = (const float*)d_in[3];
    const float* k_b = (const float*)d_in[4];
    const float* v_w = (const float*)d_in[5];
    const float* v_b = (const float*)d_in[6];
    const float* o_w = (const float*)d_in[7];
    float* out = (float*)d_out;

    float *qp, *kp, *vp, *ap, *cp, *sp;
    cudaGetSymbolAddress((void**)&qp, g_q);
    cudaGetSymbolAddress((void**)&kp, g_k);
    cudaGetSymbolAddress((void**)&vp, g_v);
    cudaGetSymbolAddress((void**)&ap, g_attn);
    cudaGetSymbolAddress((void**)&cp, g_cos);
    cudaGetSymbolAddress((void**)&sp, g_sin);

    // RoPE table
    rope_table_kernel<<<(S_ * 64 + 255) / 256, 256>>>(cp, sp);

    // QKV projections
    dim3 gq(HID_ / GBN, ROWS_ / GBM);
    dim3 gkv((NKV_ * HD_) / GBN, ROWS_ / GBM);
    sgemm_bias_kernel<<<gq, 256>>>(hs, q_w, q_b, qp, ROWS_, NH_ * HD_, HID_);
    sgemm_bias_kernel<<<gkv, 256>>>(hs, k_w, k_b, kp, ROWS_, NKV_ * HD_, HID_);
    sgemm_bias_kernel<<<gkv, 256>>>(hs, v_w, v_b, vp, ROWS_, NKV_ * HD_, HID_);

    // RoPE
    rope_apply_kernel<<<(ROWS_ * NH_ * 64 + 255) / 256, 256>>>(qp, cp, sp, NH_);
    rope_apply_kernel<<<(ROWS_ * NKV_ * 64 + 255) / 256, 256>>>(kp, cp, sp, NKV_);

    // Flash attention
    static bool attr_set = false;  // idempotent attribute set (not a work guard)
    cudaFuncSetAttribute(flash_kernel, cudaFuncAttributeMaxDynamicSharedMemorySize,
                         FLASH_SMEM_BYTES);
    (void)attr_set;
    dim3 gf(S_ / 64, NH_, B_);
    flash_kernel<<<gf, 256, FLASH_SMEM_BYTES>>>(qp, kp, vp, ap);

    // Output projection (no bias)
    sgemm_bias_kernel<<<gq, 256>>>(ap, o_w, nullptr, out, ROWS_, HID_, NH_ * HD_);
}

// round 3
// speedup vs baseline: 1.4328x; 1.4328x over previous
#include <cuda_runtime.h>
#include <cuda_bf16.h>
#include <math.h>
#include <math_constants.h>
#include <cstdint>

// Problem constants
#define B_   2
#define S_   2048
#define HID_ 2048
#define NH_  16
#define NKV_ 4
#define HD_  128
#define ROWS_ (B_ * S_)          // 4096

// ---------------- scratch (device globals; no allocation allowed) ----------
__device__ float g_q[ROWS_ * NH_ * HD_];     // 4096 x 2048
__device__ float g_k[ROWS_ * NKV_ * HD_];    // 4096 x 512
__device__ float g_v[ROWS_ * NKV_ * HD_];    // 4096 x 512
__device__ float g_attn[ROWS_ * NH_ * HD_];  // 4096 x 2048
__device__ float g_cos[S_ * 64];
__device__ float g_sin[S_ * 64];

// bf16 split operands for flash attention
__device__ __nv_bfloat16 g_qh[B_ * NH_ * S_ * HD_];   // [b][h][s][d]
__device__ __nv_bfloat16 g_ql[B_ * NH_ * S_ * HD_];
__device__ __nv_bfloat16 g_kh[B_ * NKV_ * S_ * HD_];  // [b][kvh][s][d]
__device__ __nv_bfloat16 g_kl[B_ * NKV_ * S_ * HD_];
__device__ __nv_bfloat16 g_vh[B_ * NKV_ * HD_ * S_];  // [b][kvh][d][s] (transposed)
__device__ __nv_bfloat16 g_vl[B_ * NKV_ * HD_ * S_];

// ====================== helpers =============================================
__device__ __forceinline__ uint32_t smem_u32(const void* p) {
    uint32_t r;
    asm("{ .reg .u64 t; cvta.to.shared.u64 t, %1; cvt.u32.u64 %0, t; }"
        : "=r"(r) : "l"(p));
    return r;
}

__device__ __forceinline__ void cp16(uint32_t dst, const void* src) {
    asm volatile("cp.async.cg.shared.global [%0], [%1], 16;"
                 :: "r"(dst), "l"(src) : "memory");
}

__device__ __forceinline__ float ex2(float x) {
    float r;
    asm("ex2.approx.f32 %0, %1;" : "=f"(r) : "f"(x));
    return r;
}

__device__ __forceinline__ void mma_bf16(float c[4], uint32_t a0, uint32_t a1,
                                         uint32_t a2, uint32_t a3,
                                         uint32_t b0, uint32_t b1) {
    asm volatile(
        "mma.sync.aligned.m16n8k16.row.col.f32.bf16.bf16.f32 "
        "{%0,%1,%2,%3}, {%4,%5,%6,%7}, {%8,%9}, {%0,%1,%2,%3};"
        : "+f"(c[0]), "+f"(c[1]), "+f"(c[2]), "+f"(c[3])
        : "r"(a0), "r"(a1), "r"(a2), "r"(a3), "r"(b0), "r"(b1));
}

// pack (x0,x1) to bf16x2 hi + residual lo (lo half = x0)
__device__ __forceinline__ void split_pack(float x0, float x1,
                                           uint32_t& hi, uint32_t& lo) {
    uint32_t h;
    asm("cvt.rn.bf16x2.f32 %0, %1, %2;" : "=r"(h) : "f"(x1), "f"(x0));
    float h0 = __uint_as_float(h << 16);
    float h1 = __uint_as_float(h & 0xFFFF0000u);
    float r0 = x0 - h0, r1 = x1 - h1;
    uint32_t l;
    asm("cvt.rn.bf16x2.f32 %0, %1, %2;" : "=r"(l) : "f"(r1), "f"(r0));
    hi = h;
    lo = l;
}

// ---------------- RoPE cos/sin table ----------------------------------------
__global__ void rope_table_kernel(float* cs, float* sn) {
    int idx = blockIdx.x * blockDim.x + threadIdx.x;
    if (idx >= S_ * 64) return;
    int s = idx >> 6;
    int p = idx & 63;
    double freq = exp(-((double)(2 * p) / (double)HD_) * log(10000.0));
    double ang = (double)s * freq;
    double sv, cv;
    sincos(ang, &sv, &cv);
    cs[idx] = (float)cv;
    sn[idx] = (float)sv;
}

// ---------------- RoPE apply (in place) -------------------------------------
__global__ void rope_apply_kernel(float* x, const float* __restrict__ cs,
                                  const float* __restrict__ sn, int heads) {
    int idx = blockIdx.x * blockDim.x + threadIdx.x;
    int total = ROWS_ * heads * 64;
    if (idx >= total) return;
    int p = idx & 63;
    int h = (idx >> 6) % heads;
    int row = idx / (64 * heads);
    int s = row & (S_ - 1);
    float c = cs[s * 64 + p];
    float sv = sn[s * 64 + p];
    float2* base = (float2*)(x + (size_t)row * heads * HD_ + h * HD_ + 2 * p);
    float2 v = *base;
    float2 o;
    o.x = v.x * c - v.y * sv;
    o.y = v.x * sv + v.y * c;
    *base = o;
}

// ---------------- SGEMM (fp32, from R1 — known good) ------------------------
#define GBM 128
#define GBN 128
#define GBK 16
#define APAD 132

__global__ __launch_bounds__(256) void sgemm_bias_kernel(
    const float* __restrict__ A, const float* __restrict__ Bm,
    const float* __restrict__ bias, float* __restrict__ C,
    int M, int N, int K) {
    __shared__ float As[GBK][APAD];
    __shared__ float Bs[GBK][GBN];

    int tid = threadIdx.x;
    int block_row = blockIdx.y * GBM;
    int block_col = blockIdx.x * GBN;
    int tr = (tid >> 4) * 8;
    int tc = (tid & 15) * 8;

    float acc[8][8];
#pragma unroll
    for (int i = 0; i < 8; i++)
#pragma unroll
        for (int j = 0; j < 8; j++) acc[i][j] = 0.0f;

    for (int k0 = 0; k0 < K; k0 += GBK) {
#pragma unroll
        for (int i = 0; i < 2; i++) {
            int idx = tid + i * 256;
            int r = idx >> 2;
            int c4 = (idx & 3) * 4;
            float4 v = *(const float4*)&A[(size_t)(block_row + r) * K + k0 + c4];
            As[c4 + 0][r] = v.x;
            As[c4 + 1][r] = v.y;
            As[c4 + 2][r] = v.z;
            As[c4 + 3][r] = v.w;
        }
#pragma unroll
        for (int i = 0; i < 2; i++) {
            int idx = tid + i * 256;
            int r = idx >> 5;
            int c4 = (idx & 31) * 4;
            *(float4*)&Bs[r][c4] = *(const float4*)&Bm[(size_t)(k0 + r) * N + block_col + c4];
        }
        __syncthreads();

#pragma unroll
        for (int k = 0; k < GBK; k++) {
            float a[8], b[8];
            float4 a0 = *(const float4*)&As[k][tr];
            float4 a1 = *(const float4*)&As[k][tr + 4];
            a[0] = a0.x; a[1] = a0.y; a[2] = a0.z; a[3] = a0.w;
            a[4] = a1.x; a[5] = a1.y; a[6] = a1.z; a[7] = a1.w;
            float4 b0 = *(const float4*)&Bs[k][tc];
            float4 b1 = *(const float4*)&Bs[k][tc + 4];
            b[0] = b0.x; b[1] = b0.y; b[2] = b0.z; b[3] = b0.w;
            b[4] = b1.x; b[5] = b1.y; b[6] = b1.z; b[7] = b1.w;
#pragma unroll
            for (int i = 0; i < 8; i++)
#pragma unroll
                for (int j = 0; j < 8; j++) acc[i][j] = fmaf(a[i], b[j], acc[i][j]);
        }
        __syncthreads();
    }

#pragma unroll
    for (int i = 0; i < 8; i++) {
        int gr = block_row + tr + i;
#pragma unroll
        for (int j = 0; j < 8; j += 4) {
            int gc = block_col + tc + j;
            float4 v;
            v.x = acc[i][j + 0];
            v.y = acc[i][j + 1];
            v.z = acc[i][j + 2];
            v.w = acc[i][j + 3];
            if (bias) {
                v.x += bias[gc + 0];
                v.y += bias[gc + 1];
                v.z += bias[gc + 2];
                v.w += bias[gc + 3];
            }
            *(float4*)&C[(size_t)gr * N + gc] = v;
        }
    }
}

// ---------------- split kernels for flash inputs ----------------------------
// Q: fp32 [b*S+s][h*128+d] -> bf16 hi/lo packed [b][h][s][d], scaled by scale*log2e
__global__ void split_q_kernel(const float* __restrict__ q,
                               uint32_t* __restrict__ qh, uint32_t* __restrict__ ql) {
    int i = blockIdx.x * blockDim.x + threadIdx.x;
    if (i >= B_ * NH_ * S_ * 64) return;
    int d2 = i & 63;
    int s = (i >> 6) & (S_ - 1);
    int h = (i >> 17) & (NH_ - 1);
    int b = i >> 21;
    const float c = (float)(0.08838834764831845 * 1.4426950408889634);
    float2 v = *(const float2*)(q + ((size_t)(b * S_ + s) * 2048 + h * 128 + d2 * 2));
    uint32_t hi, lo;
    split_pack(v.x * c, v.y * c, hi, lo);
    qh[i] = hi;
    ql[i] = lo;
}

// K: fp32 [b*S+s][kvh*128+d] -> bf16 hi/lo [b][kvh][s][d]
__global__ void split_k_kernel(const float* __restrict__ k,
                               uint32_t* __restrict__ kh, uint32_t* __restrict__ kl) {
    int i = blockIdx.x * blockDim.x + threadIdx.x;
    if (i >= B_ * NKV_ * S_ * 64) return;
    int d2 = i & 63;
    int s = (i >> 6) & (S_ - 1);
    int h = (i >> 17) & (NKV_ - 1);
    int b = i >> 19;
    float2 v = *(const float2*)(k + ((size_t)(b * S_ + s) * 512 + h * 128 + d2 * 2));
    uint32_t hi, lo;
    split_pack(v.x, v.y, hi, lo);
    kh[i] = hi;
    kl[i] = lo;
}

// V: fp32 [b*S+s][kvh*128+d] -> bf16 hi/lo TRANSPOSED [b][kvh][d][s]
__global__ void split_vt_kernel(const float* __restrict__ v,
                                __nv_bfloat16* __restrict__ vh,
                                __nv_bfloat16* __restrict__ vl) {
    __shared__ float t[32][33];
    int bk = blockIdx.z;               // b*NKV + kvh
    int b = bk >> 2, kvh = bk & 3;
    int s0 = blockIdx.x * 32, d0 = blockIdx.y * 32;
    int tx = threadIdx.x, ty = threadIdx.y;  // (32,8)
#pragma unroll
    for (int i = 0; i < 32; i += 8)
        t[ty + i][tx] = v[((size_t)(b * S_ + s0 + ty + i)) * 512 + kvh * 128 + d0 + tx];
    __syncthreads();
#pragma unroll
    for (int i = 0; i < 32; i += 8) {
        float x = t[tx][ty + i];                 // row s0+tx, col d0+ty+i
        __nv_bfloat16 hb = __float2bfloat16(x);
        size_t o = ((size_t)bk * 128 + d0 + ty + i) * (size_t)S_ + s0 + tx;
        vh[o] = hb;
        vl[o] = __float2bfloat16(x - __bfloat162float(hb));
    }
}

// ---------------- Flash attention (HMMA, bf16 3-term split) -----------------
// CTA: 128 q rows, 8 warps (warp w -> rows 16w..16w+15). KV tiles of 64,
// double-buffered. HD=128.
// smem layout (bytes):
//   Ql  [128][136] bf16 @ 0        (34816)
//   Qh  [128][136] bf16 @ 34816    (34816)
//   2 stages @ 69632 + s*71680:
//     Kh [64][136]  (17408) | Kl +17408 | Vh [128][72] +34816 (18432) | Vl +53248
#define FL_QL 0
#define FL_QH 34816
#define FL_STG 69632
#define FL_STG_BYTES 71680
#define FL_KL 17408
#define FL_VH 34816
#define FL_VL 53248
#define FL_SMEM (FL_STG + 2 * FL_STG_BYTES)   // 212992
#define NEGINF_F (__int_as_float(0xff800000))

__global__ __launch_bounds__(256, 1) void flash_hmma_kernel(
    const __nv_bfloat16* __restrict__ qhg, const __nv_bfloat16* __restrict__ qlg,
    const __nv_bfloat16* __restrict__ khg, const __nv_bfloat16* __restrict__ klg,
    const __nv_bfloat16* __restrict__ vhg, const __nv_bfloat16* __restrict__ vlg,
    float* __restrict__ out) {
    int qt = gridDim.x - 1 - blockIdx.x;   // heavy tiles first
    int h = blockIdx.y;
    int b = blockIdx.z;
    int kvh = h >> 2;
    int bh = b * NH_ + h;
    int bk = b * NKV_ + kvh;

    extern __shared__ __align__(16) char sm[];
    uint32_t sbase = smem_u32(sm);
    const uint32_t* QlW = (const uint32_t*)(sm + FL_QL);
    const uint32_t* QhW = (const uint32_t*)(sm + FL_QH);

    int tid = threadIdx.x;
    int w = tid >> 5, lane = tid & 31;
    int g = lane >> 2, t = lane & 3;

    // ---- issue Q loads (group 0)
    {
        const __nv_bfloat16* qh_g = qhg + ((size_t)bh * S_ + qt * 128) * 128;
        const __nv_bfloat16* ql_g = qlg + ((size_t)bh * S_ + qt * 128) * 128;
#pragma unroll
        for (int i = 0; i < 8; i++) {
            int c = tid + i * 256;
            int row = c >> 4, c16 = c & 15;
            cp16(sbase + FL_QH + row * 272 + c16 * 16, qh_g + row * 128 + c16 * 8);
            cp16(sbase + FL_QL + row * 272 + c16 * 16, ql_g + row * 128 + c16 * 8);
        }
        asm volatile("cp.async.commit_group;" ::: "memory");
    }

    const __nv_bfloat16* kh_b = khg + (size_t)bk * S_ * 128;
    const __nv_bfloat16* kl_b = klg + (size_t)bk * S_ * 128;
    const __nv_bfloat16* vh_b = vhg + (size_t)bk * 128 * S_;
    const __nv_bfloat16* vl_b = vlg + (size_t)bk * 128 * S_;

    auto load_kv = [&](int jt, int stg) {
        uint32_t sb = sbase + FL_STG + stg * FL_STG_BYTES;
#pragma unroll
        for (int i = 0; i < 4; i++) {
            int c = tid + i * 256;
            int row = c >> 4, c16 = c & 15;
            size_t go = ((size_t)(jt * 64 + row)) * 128 + c16 * 8;
            cp16(sb + row * 272 + c16 * 16, kh_b + go);
            cp16(sb + FL_KL + row * 272 + c16 * 16, kl_b + go);
        }
#pragma unroll
        for (int i = 0; i < 4; i++) {
            int c = tid + i * 256;
            int row = c >> 3, c8 = c & 7;
            size_t go = (size_t)row * S_ + jt * 64 + c8 * 8;
            cp16(sb + FL_VH + row * 144 + c8 * 16, vh_b + go);
            cp16(sb + FL_VL + row * 144 + c8 * 16, vl_b + go);
        }
        asm volatile("cp.async.commit_group;" ::: "memory");
    };

    int njt = 2 * qt + 2;
    load_kv(0, 0);
    load_kv(1, 1);
    asm volatile("cp.async.wait_group 2;" ::: "memory");
    __syncthreads();

    float o_[16][4];
#pragma unroll
    for (int n = 0; n < 16; n++)
#pragma unroll
        for (int j = 0; j < 4; j++) o_[n][j] = 0.0f;
    float m0 = NEGINF_F, m1 = NEGINF_F, l0 = 0.0f, l1 = 0.0f;

    for (int jt = 0; jt < njt; jt++) {
        if (jt < njt - 1)
            asm volatile("cp.async.wait_group 1;" ::: "memory");
        else
            asm volatile("cp.async.wait_group 0;" ::: "memory");
        __syncthreads();

        const uint32_t* KhW = (const uint32_t*)(sm + FL_STG + (jt & 1) * FL_STG_BYTES);
        const uint32_t* KlW = KhW + FL_KL / 4;
        const uint32_t* VhW = KhW + FL_VH / 4;
        const uint32_t* VlW = KhW + FL_VL / 4;

        float s[8][4];
#pragma unroll
        for (int j = 0; j < 8; j++)
#pragma unroll
            for (int x = 0; x < 4; x++) s[j][x] = 0.0f;

        // S = Q K^T (3-term split)
        for (int kk = 0; kk < 8; kk++) {
            int qi = (w * 16 + g) * 68 + kk * 8 + t;
            uint32_t qh0 = QhW[qi], qh1 = QhW[qi + 8 * 68];
            uint32_t qh2 = QhW[qi + 4], qh3 = QhW[qi + 8 * 68 + 4];
            uint32_t ql0 = QlW[qi], ql1 = QlW[qi + 8 * 68];
            uint32_t ql2 = QlW[qi + 4], ql3 = QlW[qi + 8 * 68 + 4];
#pragma unroll
            for (int j = 0; j < 8; j++) {
                int ki = (8 * j + g) * 68 + kk * 8 + t;
                uint32_t kb0 = KhW[ki], kb1 = KhW[ki + 4];
                uint32_t lb0 = KlW[ki], lb1 = KlW[ki + 4];
                mma_bf16(s[j], qh0, qh1, qh2, qh3, kb0, kb1);
                mma_bf16(s[j], qh0, qh1, qh2, qh3, lb0, lb1);
                mma_bf16(s[j], ql0, ql1, ql2, ql3, kb0, kb1);
            }
        }

        // causal mask (warp-uniform predicate)
        if (jt * 64 + 63 > qt * 128 + w * 16) {
            int row0 = qt * 128 + w * 16 + g;
            int row1 = row0 + 8;
#pragma unroll
            for (int j = 0; j < 8; j++) {
                int col = jt * 64 + 8 * j + 2 * t;
                if (col > row0) s[j][0] = NEGINF_F;
                if (col + 1 > row0) s[j][1] = NEGINF_F;
                if (col > row1) s[j][2] = NEGINF_F;
                if (col + 1 > row1) s[j][3] = NEGINF_F;
            }
        }

        // online softmax (log2 domain; Q pre-scaled by scale*log2e)
        float mx0 = NEGINF_F, mx1 = NEGINF_F;
#pragma unroll
        for (int j = 0; j < 8; j++) {
            mx0 = fmaxf(mx0, fmaxf(s[j][0], s[j][1]));
            mx1 = fmaxf(mx1, fmaxf(s[j][2], s[j][3]));
        }
        mx0 = fmaxf(mx0, __shfl_xor_sync(0xffffffff, mx0, 1));
        mx0 = fmaxf(mx0, __shfl_xor_sync(0xffffffff, mx0, 2));
        mx1 = fmaxf(mx1, __shfl_xor_sync(0xffffffff, mx1, 1));
        mx1 = fmaxf(mx1, __shfl_xor_sync(0xffffffff, mx1, 2));
        float mn0 = fmaxf(m0, mx0), mn1 = fmaxf(m1, mx1);
        float a0 = ex2(m0 - mn0), a1 = ex2(m1 - mn1);
        m0 = mn0;
        m1 = mn1;
        float sum0 = 0.0f, sum1 = 0.0f;
#pragma unroll
        for (int j = 0; j < 8; j++) {
            s[j][0] = ex2(s[j][0] - mn0);
            s[j][1] = ex2(s[j][1] - mn0);
            s[j][2] = ex2(s[j][2] - mn1);
            s[j][3] = ex2(s[j][3] - mn1);
            sum0 += s[j][0] + s[j][1];
            sum1 += s[j][2] + s[j][3];
        }
        sum0 += __shfl_xor_sync(0xffffffff, sum0, 1);
        sum0 += __shfl_xor_sync(0xffffffff, sum0, 2);
        sum1 += __shfl_xor_sync(0xffffffff, sum1, 1);
        sum1 += __shfl_xor_sync(0xffffffff, sum1, 2);
        l0 = l0 * a0 + sum0;
        l1 = l1 * a1 + sum1;
#pragma unroll
        for (int n = 0; n < 16; n++) {
            o_[n][0] *= a0;
            o_[n][1] *= a0;
            o_[n][2] *= a1;
            o_[n][3] *= a1;
        }

        // O += P V (3-term split, P fragments straight from registers)
#pragma unroll
        for (int kk = 0; kk < 4; kk++) {
            uint32_t pa0, pa1, pa2, pa3, la0, la1, la2, la3;
            split_pack(s[2 * kk][0], s[2 * kk][1], pa0, la0);
            split_pack(s[2 * kk][2], s[2 * kk][3], pa1, la1);
            split_pack(s[2 * kk + 1][0], s[2 * kk + 1][1], pa2, la2);
            split_pack(s[2 * kk + 1][2], s[2 * kk + 1][3], pa3, la3);
#pragma unroll
            for (int n = 0; n < 16; n++) {
                int vi = (8 * n + g) * 36 + kk * 8 + t;
                uint32_t vb0 = VhW[vi], vb1 = VhW[vi + 4];
                uint32_t wb0 = VlW[vi], wb1 = VlW[vi + 4];
                mma_bf16(o_[n], pa0, pa1, pa2, pa3, vb0, vb1);
                mma_bf16(o_[n], pa0, pa1, pa2, pa3, wb0, wb1);
                mma_bf16(o_[n], la0, la1, la2, la3, vb0, vb1);
            }
        }

        __syncthreads();
        if (jt + 2 < njt) load_kv(jt + 2, jt & 1);
    }

    // epilogue
    float inv0 = 1.0f / l0, inv1 = 1.0f / l1;
    int row0 = qt * 128 + w * 16 + g;
    int row1 = row0 + 8;
#pragma unroll
    for (int n = 0; n < 16; n++) {
        int col = h * 128 + 8 * n + 2 * t;
        float2 v0, v1;
        v0.x = o_[n][0] * inv0;
        v0.y = o_[n][1] * inv0;
        v1.x = o_[n][2] * inv1;
        v1.y = o_[n][3] * inv1;
        *(float2*)(out + ((size_t)(b * S_ + row0)) * 2048 + col) = v0;
        *(float2*)(out + ((size_t)(b * S_ + row1)) * 2048 + col) = v1;
    }
}

// ---------------- launch ----------------------------------------------------
extern "C" void kernel_launch(void* const* d_in, const int* in_sizes, int n_in,
                              void* d_out, int out_size) {
    const float* hs  = (const float*)d_in[0];
    const float* q_w = (const float*)d_in[1];
    const float* q_b = (const float*)d_in[2];
    const float* k_w = (const float*)d_in[3];
    const float* k_b = (const float*)d_in[4];
    const float* v_w = (const float*)d_in[5];
    const float* v_b = (const float*)d_in[6];
    const float* o_w = (const float*)d_in[7];
    float* out = (float*)d_out;

    float *qp, *kp, *vp, *ap, *cp, *sp;
    cudaGetSymbolAddress((void**)&qp, g_q);
    cudaGetSymbolAddress((void**)&kp, g_k);
    cudaGetSymbolAddress((void**)&vp, g_v);
    cudaGetSymbolAddress((void**)&ap, g_attn);
    cudaGetSymbolAddress((void**)&cp, g_cos);
    cudaGetSymbolAddress((void**)&sp, g_sin);

    __nv_bfloat16 *qh, *ql, *kh, *kl, *vh, *vl;
    cudaGetSymbolAddress((void**)&qh, g_qh);
    cudaGetSymbolAddress((void**)&ql, g_ql);
    cudaGetSymbolAddress((void**)&kh, g_kh);
    cudaGetSymbolAddress((void**)&kl, g_kl);
    cudaGetSymbolAddress((void**)&vh, g_vh);
    cudaGetSymbolAddress((void**)&vl, g_vl);

    cudaFuncSetAttribute(flash_hmma_kernel,
                         cudaFuncAttributeMaxDynamicSharedMemorySize, FL_SMEM);

    // RoPE table
    rope_table_kernel<<<(S_ * 64 + 255) / 256, 256>>>(cp, sp);

    // QKV projections (fp32)
    dim3 gq(HID_ / GBN, ROWS_ / GBM);
    dim3 gkv((NKV_ * HD_) / GBN, ROWS_ / GBM);
    sgemm_bias_kernel<<<gq, 256>>>(hs, q_w, q_b, qp, ROWS_, NH_ * HD_, HID_);
    sgemm_bias_kernel<<<gkv, 256>>>(hs, k_w, k_b, kp, ROWS_, NKV_ * HD_, HID_);
    sgemm_bias_kernel<<<gkv, 256>>>(hs, v_w, v_b, vp, ROWS_, NKV_ * HD_, HID_);

    // RoPE
    rope_apply_kernel<<<(ROWS_ * NH_ * 64 + 255) / 256, 256>>>(qp, cp, sp, NH_);
    rope_apply_kernel<<<(ROWS_ * NKV_ * 64 + 255) / 256, 256>>>(kp, cp, sp, NKV_);

    // Split to bf16 hi/lo (Q pre-scaled by scale*log2e)
    split_q_kernel<<<(B_ * NH_ * S_ * 64 + 255) / 256, 256>>>(qp, (uint32_t*)qh,
                                                              (uint32_t*)ql);
    split_k_kernel<<<(B_ * NKV_ * S_ * 64 + 255) / 256, 256>>>(kp, (uint32_t*)kh,
                                                               (uint32_t*)kl);
    dim3 tv(32, 8);
    split_vt_kernel<<<dim3(S_ / 32, HD_ / 32, B_ * NKV_), tv>>>(vp, vh, vl);

    // Flash attention (HMMA)
    dim3 gf(S_ / 128, NH_, B_);
    flash_hmma_kernel<<<gf, 256, FL_SMEM>>>(qh, ql, kh, kl, vh, vl, ap);

    // Output projection (fp32)
    sgemm_bias_kernel<<<gq, 256>>>(ap, o_w, nullptr, out, ROWS_, HID_, NH_ * HD_);
}

// round 4
// speedup vs baseline: 2.6690x; 1.8628x over previous
#include <cuda_runtime.h>
#include <cuda_bf16.h>
#include <math.h>
#include <math_constants.h>
#include <cstdint>

// Problem constants
#define B_   2
#define S_   2048
#define HID_ 2048
#define NH_  16
#define NKV_ 4
#define HD_  128
#define ROWS_ (B_ * S_)          // 4096

// ---------------- scratch (device globals; no allocation allowed) ----------
__device__ float g_q[ROWS_ * NH_ * HD_];     // 4096 x 2048
__device__ float g_k[ROWS_ * NKV_ * HD_];    // 4096 x 512
__device__ float g_v[ROWS_ * NKV_ * HD_];    // 4096 x 512
__device__ float g_attn[ROWS_ * NH_ * HD_];  // 4096 x 2048
__device__ float g_cos[S_ * 64];
__device__ float g_sin[S_ * 64];

// bf16 split operands for GEMMs
__device__ __nv_bfloat16 g_hs_h[ROWS_ * HID_];
__device__ __nv_bfloat16 g_hs_l[ROWS_ * HID_];
__device__ __nv_bfloat16 g_at_h[ROWS_ * HID_];
__device__ __nv_bfloat16 g_at_l[ROWS_ * HID_];
__device__ __nv_bfloat16 g_qw_h[2048 * 2048];  // [N,K]
__device__ __nv_bfloat16 g_qw_l[2048 * 2048];
__device__ __nv_bfloat16 g_kw_h[512 * 2048];
__device__ __nv_bfloat16 g_kw_l[512 * 2048];
__device__ __nv_bfloat16 g_vw_h[512 * 2048];
__device__ __nv_bfloat16 g_vw_l[512 * 2048];
__device__ __nv_bfloat16 g_ow_h[2048 * 2048];
__device__ __nv_bfloat16 g_ow_l[2048 * 2048];

// bf16 split operands for flash attention
__device__ __nv_bfloat16 g_qh[B_ * NH_ * S_ * HD_];   // [b][h][s][d]
__device__ __nv_bfloat16 g_ql[B_ * NH_ * S_ * HD_];
__device__ __nv_bfloat16 g_kh[B_ * NKV_ * S_ * HD_];  // [b][kvh][s][d]
__device__ __nv_bfloat16 g_kl[B_ * NKV_ * S_ * HD_];
__device__ __nv_bfloat16 g_vh[B_ * NKV_ * HD_ * S_];  // [b][kvh][d][s]
__device__ __nv_bfloat16 g_vl[B_ * NKV_ * HD_ * S_];

// ====================== helpers =============================================
__device__ __forceinline__ uint32_t smem_u32(const void* p) {
    uint32_t r;
    asm("{ .reg .u64 t; cvta.to.shared.u64 t, %1; cvt.u32.u64 %0, t; }"
        : "=r"(r) : "l"(p));
    return r;
}

__device__ __forceinline__ void cp16(uint32_t dst, const void* src) {
    asm volatile("cp.async.cg.shared.global [%0], [%1], 16;"
                 :: "r"(dst), "l"(src) : "memory");
}

__device__ __forceinline__ float ex2(float x) {
    float r;
    asm("ex2.approx.f32 %0, %1;" : "=f"(r) : "f"(x));
    return r;
}

__device__ __forceinline__ void mma_bf16(float c[4], uint32_t a0, uint32_t a1,
                                         uint32_t a2, uint32_t a3,
                                         uint32_t b0, uint32_t b1) {
    asm volatile(
        "mma.sync.aligned.m16n8k16.row.col.f32.bf16.bf16.f32 "
        "{%0,%1,%2,%3}, {%4,%5,%6,%7}, {%8,%9}, {%0,%1,%2,%3};"
        : "+f"(c[0]), "+f"(c[1]), "+f"(c[2]), "+f"(c[3])
        : "r"(a0), "r"(a1), "r"(a2), "r"(a3), "r"(b0), "r"(b1));
}

__device__ __forceinline__ void ldsm4(uint32_t a[4], uint32_t addr) {
    asm volatile("ldmatrix.sync.aligned.m8n8.x4.shared.b16 {%0,%1,%2,%3}, [%4];"
                 : "=r"(a[0]), "=r"(a[1]), "=r"(a[2]), "=r"(a[3]) : "r"(addr));
}

__device__ __forceinline__ void ldsm2(uint32_t a[2], uint32_t addr) {
    asm volatile("ldmatrix.sync.aligned.m8n8.x2.shared.b16 {%0,%1}, [%2];"
                 : "=r"(a[0]), "=r"(a[1]) : "r"(addr));
}

// pack (x0,x1) to bf16x2 hi + residual lo
__device__ __forceinline__ void split_pack(float x0, float x1,
                                           uint32_t& hi, uint32_t& lo) {
    uint32_t h;
    asm("cvt.rn.bf16x2.f32 %0, %1, %2;" : "=r"(h) : "f"(x1), "f"(x0));
    float h0 = __uint_as_float(h << 16);
    float h1 = __uint_as_float(h & 0xFFFF0000u);
    float r0 = x0 - h0, r1 = x1 - h1;
    uint32_t l;
    asm("cvt.rn.bf16x2.f32 %0, %1, %2;" : "=r"(l) : "f"(r1), "f"(r0));
    hi = h;
    lo = l;
}

// ---------------- RoPE cos/sin table ----------------------------------------
__global__ void rope_table_kernel(float* cs, float* sn) {
    int idx = blockIdx.x * blockDim.x + threadIdx.x;
    if (idx >= S_ * 64) return;
    int s = idx >> 6;
    int p = idx & 63;
    double freq = exp(-((double)(2 * p) / (double)HD_) * log(10000.0));
    double ang = (double)s * freq;
    double sv, cv;
    sincos(ang, &sv, &cv);
    cs[idx] = (float)cv;
    sn[idx] = (float)sv;
}

// ---------------- RoPE apply (in place) -------------------------------------
__global__ void rope_apply_kernel(float* x, const float* __restrict__ cs,
                                  const float* __restrict__ sn, int heads) {
    int idx = blockIdx.x * blockDim.x + threadIdx.x;
    int total = ROWS_ * heads * 64;
    if (idx >= total) return;
    int p = idx & 63;
    int h = (idx >> 6) % heads;
    int row = idx / (64 * heads);
    int s = row & (S_ - 1);
    float c = cs[s * 64 + p];
    float sv = sn[s * 64 + p];
    float2* base = (float2*)(x + (size_t)row * heads * HD_ + h * HD_ + 2 * p);
    float2 v = *base;
    float2 o;
    o.x = v.x * c - v.y * sv;
    o.y = v.x * sv + v.y * c;
    *base = o;
}

// ================= HMMA split-bf16 GEMM =====================================
// C[M,N] = A[M,K] @ Bt[N,K]^T (+bias). A/Bt pre-split bf16 hi/lo.
// BM=128 BN=128 BK=32, 256 threads (8 warps, 2x4), warp tile 64x32.
// smem stage: Ah[128][144B] | Al | Bh | Bl  (pitch 144B = 36 words, row=32 bf16)
#define HG_SA_L 18432
#define HG_SB_H 36864
#define HG_SB_L 55296
#define HG_STAGE 73728
#define HG_SMEM (2 * HG_STAGE)   // 147456

__global__ __launch_bounds__(256, 1) void hgemm_kernel(
    const __nv_bfloat16* __restrict__ Ah, const __nv_bfloat16* __restrict__ Al,
    const __nv_bfloat16* __restrict__ Bh, const __nv_bfloat16* __restrict__ Bl,
    const float* __restrict__ bias, float* __restrict__ C,
    int M, int N, int K) {
    extern __shared__ __align__(16) char smc[];
    uint32_t sb = smem_u32(smc);
    int tid = threadIdx.x, wid = tid >> 5, lane = tid & 31;
    int warp_m = wid >> 2, warp_n = wid & 3;
    int m0 = blockIdx.y * 128, n0 = blockIdx.x * 128;
    int g = lane >> 2, t = lane & 3;

    // ldmatrix per-lane offsets
    int r8 = lane & 7, sel = lane >> 3;
    uint32_t aoff = (uint32_t)((warp_m * 64 + (sel & 1) * 8 + r8) * 144 +
                               (sel >> 1) * 16);
    uint32_t boff = (uint32_t)((warp_n * 32 + r8) * 144 + (sel & 1) * 16);

    auto load_stage = [&](int k0, int stg) {
        uint32_t st = sb + stg * HG_STAGE;
#pragma unroll
        for (int i = 0; i < 2; i++) {
            int idx = tid + i * 256;
            int row = idx >> 2, seg = idx & 3;
            uint32_t so = row * 144 + seg * 16;
            size_t ga = (size_t)(m0 + row) * K + k0 + seg * 8;
            size_t gb = (size_t)(n0 + row) * K + k0 + seg * 8;
            cp16(st + so, Ah + ga);
            cp16(st + HG_SA_L + so, Al + ga);
            cp16(st + HG_SB_H + so, Bh + gb);
            cp16(st + HG_SB_L + so, Bl + gb);
        }
        asm volatile("cp.async.commit_group;" ::: "memory");
    };

    float acc[4][4][4];
#pragma unroll
    for (int i = 0; i < 4; i++)
#pragma unroll
        for (int j = 0; j < 4; j++)
#pragma unroll
            for (int x = 0; x < 4; x++) acc[i][j][x] = 0.0f;

    const int niter = K / 32;
    load_stage(0, 0);
    load_stage(32, 1);

    for (int it = 0; it < niter; it++) {
        if (it < niter - 1)
            asm volatile("cp.async.wait_group 1;" ::: "memory");
        else
            asm volatile("cp.async.wait_group 0;" ::: "memory");
        __syncthreads();
        uint32_t st = sb + (it & 1) * HG_STAGE;

#pragma unroll
        for (int kc = 0; kc < 2; kc++) {
            uint32_t ah[4][4], al[4][4], bh[4][2], bl[4][2];
#pragma unroll
            for (int fm = 0; fm < 4; fm++) {
                ldsm4(ah[fm], st + aoff + fm * 2304 + kc * 32);
                ldsm4(al[fm], st + HG_SA_L + aoff + fm * 2304 + kc * 32);
            }
#pragma unroll
            for (int fn = 0; fn < 4; fn++) {
                ldsm2(bh[fn], st + HG_SB_H + boff + fn * 1152 + kc * 32);
                ldsm2(bl[fn], st + HG_SB_L + boff + fn * 1152 + kc * 32);
            }
#pragma unroll
            for (int fm = 0; fm < 4; fm++)
#pragma unroll
                for (int fn = 0; fn < 4; fn++) {
                    mma_bf16(acc[fm][fn], ah[fm][0], ah[fm][1], ah[fm][2],
                             ah[fm][3], bh[fn][0], bh[fn][1]);
                    mma_bf16(acc[fm][fn], ah[fm][0], ah[fm][1], ah[fm][2],
                             ah[fm][3], bl[fn][0], bl[fn][1]);
                    mma_bf16(acc[fm][fn], al[fm][0], al[fm][1], al[fm][2],
                             al[fm][3], bh[fn][0], bh[fn][1]);
                }
        }
        __syncthreads();
        if (it + 2 < niter) load_stage((it + 2) * 32, it & 1);
    }

    // epilogue
#pragma unroll
    for (int fm = 0; fm < 4; fm++) {
        int row0 = m0 + warp_m * 64 + fm * 16 + g;
        int row1 = row0 + 8;
#pragma unroll
        for (int fn = 0; fn < 4; fn++) {
            int col = n0 + warp_n * 32 + fn * 8 + 2 * t;
            float bx = 0.0f, by = 0.0f;
            if (bias) {
                float2 bb = *(const float2*)(bias + col);
                bx = bb.x;
                by = bb.y;
            }
            float2 v0, v1;
            v0.x = acc[fm][fn][0] + bx;
            v0.y = acc[fm][fn][1] + by;
            v1.x = acc[fm][fn][2] + bx;
            v1.y = acc[fm][fn][3] + by;
            *(float2*)(C + (size_t)row0 * N + col) = v0;
            *(float2*)(C + (size_t)row1 * N + col) = v1;
        }
    }
}

// ---------------- conversion kernels ----------------------------------------
__global__ void split_kernel(const float* __restrict__ x,
                             __nv_bfloat16* __restrict__ h,
                             __nv_bfloat16* __restrict__ l, int n4) {
    int i = blockIdx.x * blockDim.x + threadIdx.x;
    if (i >= n4) return;
    float4 v = ((const float4*)x)[i];
    uint32_t h0, l0, h1, l1;
    split_pack(v.x, v.y, h0, l0);
    split_pack(v.z, v.w, h1, l1);
    ((uint32_t*)h)[i * 2 + 0] = h0;
    ((uint32_t*)h)[i * 2 + 1] = h1;
    ((uint32_t*)l)[i * 2 + 0] = l0;
    ((uint32_t*)l)[i * 2 + 1] = l1;
}

// W [K,N] fp32 -> Th/Tl [N,K] bf16
__global__ void transpose_split_kernel(const float* __restrict__ W,
                                       __nv_bfloat16* __restrict__ Th,
                                       __nv_bfloat16* __restrict__ Tl,
                                       int K, int N) {
    __shared__ float tshm[32][33];
    int n0 = blockIdx.x * 32, k0 = blockIdx.y * 32;
    int tx = threadIdx.x, ty = threadIdx.y;  // (32,8)
#pragma unroll
    for (int i = 0; i < 32; i += 8)
        tshm[ty + i][tx] = W[(size_t)(k0 + ty + i) * N + n0 + tx];
    __syncthreads();
#pragma unroll
    for (int i = 0; i < 32; i += 8) {
        int n = n0 + ty + i, k = k0 + tx;
        float v = tshm[tx][ty + i];
        __nv_bfloat16 hb = __float2bfloat16(v);
        Th[(size_t)n * K + k] = hb;
        Tl[(size_t)n * K + k] = __float2bfloat16(v - __bfloat162float(hb));
    }
}

// Q: fp32 -> bf16 hi/lo [b][h][s][d], scaled by scale*log2e
__global__ void split_q_kernel(const float* __restrict__ q,
                               uint32_t* __restrict__ qh, uint32_t* __restrict__ ql) {
    int i = blockIdx.x * blockDim.x + threadIdx.x;
    if (i >= B_ * NH_ * S_ * 64) return;
    int d2 = i & 63;
    int s = (i >> 6) & (S_ - 1);
    int h = (i >> 17) & (NH_ - 1);
    int b = i >> 21;
    const float c = (float)(0.08838834764831845 * 1.4426950408889634);
    float2 v = *(const float2*)(q + ((size_t)(b * S_ + s) * 2048 + h * 128 + d2 * 2));
    uint32_t hi, lo;
    split_pack(v.x * c, v.y * c, hi, lo);
    qh[i] = hi;
    ql[i] = lo;
}

__global__ void split_k_kernel(const float* __restrict__ k,
                               uint32_t* __restrict__ kh, uint32_t* __restrict__ kl) {
    int i = blockIdx.x * blockDim.x + threadIdx.x;
    if (i >= B_ * NKV_ * S_ * 64) return;
    int d2 = i & 63;
    int s = (i >> 6) & (S_ - 1);
    int h = (i >> 17) & (NKV_ - 1);
    int b = i >> 19;
    float2 v = *(const float2*)(k + ((size_t)(b * S_ + s) * 512 + h * 128 + d2 * 2));
    uint32_t hi, lo;
    split_pack(v.x, v.y, hi, lo);
    kh[i] = hi;
    kl[i] = lo;
}

// V: fp32 -> bf16 hi/lo TRANSPOSED [b][kvh][d][s]
__global__ void split_vt_kernel(const float* __restrict__ v,
                                __nv_bfloat16* __restrict__ vh,
                                __nv_bfloat16* __restrict__ vl) {
    __shared__ float tshm[32][33];
    int bk = blockIdx.z;
    int b = bk >> 2, kvh = bk & 3;
    int s0 = blockIdx.x * 32, d0 = blockIdx.y * 32;
    int tx = threadIdx.x, ty = threadIdx.y;
#pragma unroll
    for (int i = 0; i < 32; i += 8)
        tshm[ty + i][tx] = v[((size_t)(b * S_ + s0 + ty + i)) * 512 + kvh * 128 + d0 + tx];
    __syncthreads();
#pragma unroll
    for (int i = 0; i < 32; i += 8) {
        float x = tshm[tx][ty + i];
        __nv_bfloat16 hb = __float2bfloat16(x);
        size_t o = ((size_t)bk * 128 + d0 + ty + i) * (size_t)S_ + s0 + tx;
        vh[o] = hb;
        vl[o] = __float2bfloat16(x - __bfloat162float(hb));
    }
}

// ---------------- Flash attention (HMMA, bf16 3-term split) -----------------
#define FL_QL 0
#define FL_QH 34816
#define FL_STG 69632
#define FL_STG_BYTES 71680
#define FL_KL 17408
#define FL_VH 34816
#define FL_VL 53248
#define FL_SMEM (FL_STG + 2 * FL_STG_BYTES)
#define NEGINF_F (__int_as_float(0xff800000))

__global__ __launch_bounds__(256, 1) void flash_hmma_kernel(
    const __nv_bfloat16* __restrict__ qhg, const __nv_bfloat16* __restrict__ qlg,
    const __nv_bfloat16* __restrict__ khg, const __nv_bfloat16* __restrict__ klg,
    const __nv_bfloat16* __restrict__ vhg, const __nv_bfloat16* __restrict__ vlg,
    float* __restrict__ out) {
    int qt = gridDim.x - 1 - blockIdx.x;
    int h = blockIdx.y;
    int b = blockIdx.z;
    int kvh = h >> 2;
    int bh = b * NH_ + h;
    int bk = b * NKV_ + kvh;

    extern __shared__ __align__(16) char sm[];
    uint32_t sbase = smem_u32(sm);
    const uint32_t* QlW = (const uint32_t*)(sm + FL_QL);
    const uint32_t* QhW = (const uint32_t*)(sm + FL_QH);

    int tid = threadIdx.x;
    int w = tid >> 5, lane = tid & 31;
    int g = lane >> 2, t = lane & 3;

    {
        const __nv_bfloat16* qh_g = qhg + ((size_t)bh * S_ + qt * 128) * 128;
        const __nv_bfloat16* ql_g = qlg + ((size_t)bh * S_ + qt * 128) * 128;
#pragma unroll
        for (int i = 0; i < 8; i++) {
            int c = tid + i * 256;
            int row = c >> 4, c16 = c & 15;
            cp16(sbase + FL_QH + row * 272 + c16 * 16, qh_g + row * 128 + c16 * 8);
            cp16(sbase + FL_QL + row * 272 + c16 * 16, ql_g + row * 128 + c16 * 8);
        }
        asm volatile("cp.async.commit_group;" ::: "memory");
    }

    const __nv_bfloat16* kh_b = khg + (size_t)bk * S_ * 128;
    const __nv_bfloat16* kl_b = klg + (size_t)bk * S_ * 128;
    const __nv_bfloat16* vh_b = vhg + (size_t)bk * 128 * S_;
    const __nv_bfloat16* vl_b = vlg + (size_t)bk * 128 * S_;

    auto load_kv = [&](int jt, int stg) {
        uint32_t sb = sbase + FL_STG + stg * FL_STG_BYTES;
#pragma unroll
        for (int i = 0; i < 4; i++) {
            int c = tid + i * 256;
            int row = c >> 4, c16 = c & 15;
            size_t go = ((size_t)(jt * 64 + row)) * 128 + c16 * 8;
            cp16(sb + row * 272 + c16 * 16, kh_b + go);
            cp16(sb + FL_KL + row * 272 + c16 * 16, kl_b + go);
        }
#pragma unroll
        for (int i = 0; i < 4; i++) {
            int c = tid + i * 256;
            int row = c >> 3, c8 = c & 7;
            size_t go = (size_t)row * S_ + jt * 64 + c8 * 8;
            cp16(sb + FL_VH + row * 144 + c8 * 16, vh_b + go);
            cp16(sb + FL_VL + row * 144 + c8 * 16, vl_b + go);
        }
        asm volatile("cp.async.commit_group;" ::: "memory");
    };

    int njt = 2 * qt + 2;
    load_kv(0, 0);
    load_kv(1, 1);
    asm volatile("cp.async.wait_group 2;" ::: "memory");
    __syncthreads();

    float o_[16][4];
#pragma unroll
    for (int n = 0; n < 16; n++)
#pragma unroll
        for (int j = 0; j < 4; j++) o_[n][j] = 0.0f;
    float m0 = NEGINF_F, m1 = NEGINF_F, l0 = 0.0f, l1 = 0.0f;

    for (int jt = 0; jt < njt; jt++) {
        if (jt < njt - 1)
            asm volatile("cp.async.wait_group 1;" ::: "memory");
        else
            asm volatile("cp.async.wait_group 0;" ::: "memory");
        __syncthreads();

        const uint32_t* KhW = (const uint32_t*)(sm + FL_STG + (jt & 1) * FL_STG_BYTES);
        const uint32_t* KlW = KhW + FL_KL / 4;
        const uint32_t* VhW = KhW + FL_VH / 4;
        const uint32_t* VlW = KhW + FL_VL / 4;

        float s[8][4];
#pragma unroll
        for (int j = 0; j < 8; j++)
#pragma unroll
            for (int x = 0; x < 4; x++) s[j][x] = 0.0f;

        for (int kk = 0; kk < 8; kk++) {
            int qi = (w * 16 + g) * 68 + kk * 8 + t;
            uint32_t qh0 = QhW[qi], qh1 = QhW[qi + 8 * 68];
            uint32_t qh2 = QhW[qi + 4], qh3 = QhW[qi + 8 * 68 + 4];
            uint32_t ql0 = QlW[qi], ql1 = QlW[qi + 8 * 68];
            uint32_t ql2 = QlW[qi + 4], ql3 = QlW[qi + 8 * 68 + 4];
#pragma unroll
            for (int j = 0; j < 8; j++) {
                int ki = (8 * j + g) * 68 + kk * 8 + t;
                uint32_t kb0 = KhW[ki], kb1 = KhW[ki + 4];
                uint32_t lb0 = KlW[ki], lb1 = KlW[ki + 4];
                mma_bf16(s[j], qh0, qh1, qh2, qh3, kb0, kb1);
                mma_bf16(s[j], qh0, qh1, qh2, qh3, lb0, lb1);
                mma_bf16(s[j], ql0, ql1, ql2, ql3, kb0, kb1);
            }
        }

        if (jt * 64 + 63 > qt * 128 + w * 16) {
            int row0 = qt * 128 + w * 16 + g;
            int row1 = row0 + 8;
#pragma unroll
            for (int j = 0; j < 8; j++) {
                int col = jt * 64 + 8 * j + 2 * t;
                if (col > row0) s[j][0] = NEGINF_F;
                if (col + 1 > row0) s[j][1] = NEGINF_F;
                if (col > row1) s[j][2] = NEGINF_F;
                if (col + 1 > row1) s[j][3] = NEGINF_F;
            }
        }

        float mx0 = NEGINF_F, mx1 = NEGINF_F;
#pragma unroll
        for (int j = 0; j < 8; j++) {
            mx0 = fmaxf(mx0, fmaxf(s[j][0], s[j][1]));
            mx1 = fmaxf(mx1, fmaxf(s[j][2], s[j][3]));
        }
        mx0 = fmaxf(mx0, __shfl_xor_sync(0xffffffff, mx0, 1));
        mx0 = fmaxf(mx0, __shfl_xor_sync(0xffffffff, mx0, 2));
        mx1 = fmaxf(mx1, __shfl_xor_sync(0xffffffff, mx1, 1));
        mx1 = fmaxf(mx1, __shfl_xor_sync(0xffffffff, mx1, 2));
        float mn0 = fmaxf(m0, mx0), mn1 = fmaxf(m1, mx1);
        float a0 = ex2(m0 - mn0), a1 = ex2(m1 - mn1);
        m0 = mn0;
        m1 = mn1;
        float sum0 = 0.0f, sum1 = 0.0f;
#pragma unroll
        for (int j = 0; j < 8; j++) {
            s[j][0] = ex2(s[j][0] - mn0);
            s[j][1] = ex2(s[j][1] - mn0);
            s[j][2] = ex2(s[j][2] - mn1);
            s[j][3] = ex2(s[j][3] - mn1);
            sum0 += s[j][0] + s[j][1];
            sum1 += s[j][2] + s[j][3];
        }
        sum0 += __shfl_xor_sync(0xffffffff, sum0, 1);
        sum0 += __shfl_xor_sync(0xffffffff, sum0, 2);
        sum1 += __shfl_xor_sync(0xffffffff, sum1, 1);
        sum1 += __shfl_xor_sync(0xffffffff, sum1, 2);
        l0 = l0 * a0 + sum0;
        l1 = l1 * a1 + sum1;
#pragma unroll
        for (int n = 0; n < 16; n++) {
            o_[n][0] *= a0;
            o_[n][1] *= a0;
            o_[n][2] *= a1;
            o_[n][3] *= a1;
        }

#pragma unroll
        for (int kk = 0; kk < 4; kk++) {
            uint32_t pa0, pa1, pa2, pa3, la0, la1, la2, la3;
            split_pack(s[2 * kk][0], s[2 * kk][1], pa0, la0);
            split_pack(s[2 * kk][2], s[2 * kk][3], pa1, la1);
            split_pack(s[2 * kk + 1][0], s[2 * kk + 1][1], pa2, la2);
            split_pack(s[2 * kk + 1][2], s[2 * kk + 1][3], pa3, la3);
#pragma unroll
            for (int n = 0; n < 16; n++) {
                int vi = (8 * n + g) * 36 + kk * 8 + t;
                uint32_t vb0 = VhW[vi], vb1 = VhW[vi + 4];
                uint32_t wb0 = VlW[vi], wb1 = VlW[vi + 4];
                mma_bf16(o_[n], pa0, pa1, pa2, pa3, vb0, vb1);
                mma_bf16(o_[n], pa0, pa1, pa2, pa3, wb0, wb1);
                mma_bf16(o_[n], la0, la1, la2, la3, vb0, vb1);
            }
        }

        __syncthreads();
        if (jt + 2 < njt) load_kv(jt + 2, jt & 1);
    }

    float inv0 = 1.0f / l0, inv1 = 1.0f / l1;
    int row0 = qt * 128 + w * 16 + g;
    int row1 = row0 + 8;
#pragma unroll
    for (int n = 0; n < 16; n++) {
        int col = h * 128 + 8 * n + 2 * t;
        float2 v0, v1;
        v0.x = o_[n][0] * inv0;
        v0.y = o_[n][1] * inv0;
        v1.x = o_[n][2] * inv1;
        v1.y = o_[n][3] * inv1;
        *(float2*)(out + ((size_t)(b * S_ + row0)) * 2048 + col) = v0;
        *(float2*)(out + ((size_t)(b * S_ + row1)) * 2048 + col) = v1;
    }
}

// ---------------- launch ----------------------------------------------------
extern "C" void kernel_launch(void* const* d_in, const int* in_sizes, int n_in,
                              void* d_out, int out_size) {
    const float* hs  = (const float*)d_in[0];
    const float* q_w = (const float*)d_in[1];
    const float* q_b = (const float*)d_in[2];
    const float* k_w = (const float*)d_in[3];
    const float* k_b = (const float*)d_in[4];
    const float* v_w = (const float*)d_in[5];
    const float* v_b = (const float*)d_in[6];
    const float* o_w = (const float*)d_in[7];
    float* out = (float*)d_out;

    float *qp, *kp, *vp, *ap, *cp, *sp;
    cudaGetSymbolAddress((void**)&qp, g_q);
    cudaGetSymbolAddress((void**)&kp, g_k);
    cudaGetSymbolAddress((void**)&vp, g_v);
    cudaGetSymbolAddress((void**)&ap, g_attn);
    cudaGetSymbolAddress((void**)&cp, g_cos);
    cudaGetSymbolAddress((void**)&sp, g_sin);

    __nv_bfloat16 *hsh, *hsl, *ath, *atl, *qwh, *qwl, *kwh, *kwl, *vwh, *vwl, *owh, *owl;
    cudaGetSymbolAddress((void**)&hsh, g_hs_h);
    cudaGetSymbolAddress((void**)&hsl, g_hs_l);
    cudaGetSymbolAddress((void**)&ath, g_at_h);
    cudaGetSymbolAddress((void**)&atl, g_at_l);
    cudaGetSymbolAddress((void**)&qwh, g_qw_h);
    cudaGetSymbolAddress((void**)&qwl, g_qw_l);
    cudaGetSymbolAddress((void**)&kwh, g_kw_h);
    cudaGetSymbolAddress((void**)&kwl, g_kw_l);
    cudaGetSymbolAddress((void**)&vwh, g_vw_h);
    cudaGetSymbolAddress((void**)&vwl, g_vw_l);
    cudaGetSymbolAddress((void**)&owh, g_ow_h);
    cudaGetSymbolAddress((void**)&owl, g_ow_l);

    __nv_bfloat16 *qh, *ql, *kh, *kl, *vh, *vl;
    cudaGetSymbolAddress((void**)&qh, g_qh);
    cudaGetSymbolAddress((void**)&ql, g_ql);
    cudaGetSymbolAddress((void**)&kh, g_kh);
    cudaGetSymbolAddress((void**)&kl, g_kl);
    cudaGetSymbolAddress((void**)&vh, g_vh);
    cudaGetSymbolAddress((void**)&vl, g_vl);

    cudaFuncSetAttribute(hgemm_kernel,
                         cudaFuncAttributeMaxDynamicSharedMemorySize, HG_SMEM);
    cudaFuncSetAttribute(flash_hmma_kernel,
                         cudaFuncAttributeMaxDynamicSharedMemorySize, FL_SMEM);

    // RoPE table
    rope_table_kernel<<<(S_ * 64 + 255) / 256, 256>>>(cp, sp);

    // Convert operands to split bf16
    int n4_hs = (ROWS_ * HID_) / 4;
    split_kernel<<<(n4_hs + 255) / 256, 256>>>(hs, hsh, hsl, n4_hs);
    dim3 tb(32, 8);
    transpose_split_kernel<<<dim3(2048 / 32, 2048 / 32), tb>>>(q_w, qwh, qwl, 2048, 2048);
    transpose_split_kernel<<<dim3(512 / 32, 2048 / 32), tb>>>(k_w, kwh, kwl, 2048, 512);
    transpose_split_kernel<<<dim3(512 / 32, 2048 / 32), tb>>>(v_w, vwh, vwl, 2048, 512);
    transpose_split_kernel<<<dim3(2048 / 32, 2048 / 32), tb>>>(o_w, owh, owl, 2048, 2048);

    // QKV projections (HMMA split-bf16)
    dim3 gq(2048 / 128, ROWS_ / 128);   // (16, 32)
    dim3 gkv(512 / 128, ROWS_ / 128);   // (4, 32)
    hgemm_kernel<<<gq, 256, HG_SMEM>>>(hsh, hsl, qwh, qwl, q_b, qp,
                                       ROWS_, NH_ * HD_, HID_);
    hgemm_kernel<<<gkv, 256, HG_SMEM>>>(hsh, hsl, kwh, kwl, k_b, kp,
                                        ROWS_, NKV_ * HD_, HID_);
    hgemm_kernel<<<gkv, 256, HG_SMEM>>>(hsh, hsl, vwh, vwl, v_b, vp,
                                        ROWS_, NKV_ * HD_, HID_);

    // RoPE
    rope_apply_kernel<<<(ROWS_ * NH_ * 64 + 255) / 256, 256>>>(qp, cp, sp, NH_);
    rope_apply_kernel<<<(ROWS_ * NKV_ * 64 + 255) / 256, 256>>>(kp, cp, sp, NKV_);

    // Split to bf16 hi/lo for flash
    split_q_kernel<<<(B_ * NH_ * S_ * 64 + 255) / 256, 256>>>(qp, (uint32_t*)qh,
                                                              (uint32_t*)ql);
    split_k_kernel<<<(B_ * NKV_ * S_ * 64 + 255) / 256, 256>>>(kp, (uint32_t*)kh,
                                                               (uint32_t*)kl);
    dim3 tv(32, 8);
    split_vt_kernel<<<dim3(S_ / 32, HD_ / 32, B_ * NKV_), tv>>>(vp, vh, vl);

    // Flash attention (HMMA)
    dim3 gf(S_ / 128, NH_, B_);
    flash_hmma_kernel<<<gf, 256, FL_SMEM>>>(qh, ql, kh, kl, vh, vl, ap);

    // Output projection (HMMA split-bf16)
    split_kernel<<<(n4_hs + 255) / 256, 256>>>(ap, ath, atl, n4_hs);
    hgemm_kernel<<<gq, 256, HG_SMEM>>>(ath, atl, owh, owl, nullptr, out,
                                       ROWS_, HID_, NH_ * HD_);
}

// round 5
// speedup vs baseline: 2.7147x; 1.0171x over previous
#include <cuda_runtime.h>
#include <cuda_bf16.h>
#include <math.h>
#include <math_constants.h>
#include <cstdint>

// Problem constants
#define B_   2
#define S_   2048
#define HID_ 2048
#define NH_  16
#define NKV_ 4
#define HD_  128
#define ROWS_ (B_ * S_)          // 4096

// Q pre-scale: 1/sqrt(128) * log2(e)
#define QSC ((float)(0.08838834764831845 * 1.4426950408889634))

// ---------------- scratch (device globals; no allocation allowed) ----------
__device__ float g_v[ROWS_ * NKV_ * HD_];    // fp32 V (pre-transpose)
__device__ float g_cos[S_ * 64];
__device__ float g_sin[S_ * 64];

// bf16 split operands
__device__ __nv_bfloat16 g_hs_h[ROWS_ * HID_];
__device__ __nv_bfloat16 g_hs_l[ROWS_ * HID_];
__device__ __nv_bfloat16 g_at_h[ROWS_ * HID_];
__device__ __nv_bfloat16 g_at_l[ROWS_ * HID_];
__device__ __nv_bfloat16 g_qw_h[2048 * 2048];  // [N,K]
__device__ __nv_bfloat16 g_qw_l[2048 * 2048];
__device__ __nv_bfloat16 g_kw_h[512 * 2048];
__device__ __nv_bfloat16 g_kw_l[512 * 2048];
__device__ __nv_bfloat16 g_vw_h[512 * 2048];
__device__ __nv_bfloat16 g_vw_l[512 * 2048];
__device__ __nv_bfloat16 g_ow_h[2048 * 2048];
__device__ __nv_bfloat16 g_ow_l[2048 * 2048];

__device__ __nv_bfloat16 g_qh[B_ * NH_ * S_ * HD_];   // [b][h][s][d]
__device__ __nv_bfloat16 g_ql[B_ * NH_ * S_ * HD_];
__device__ __nv_bfloat16 g_kh[B_ * NKV_ * S_ * HD_];  // [b][kvh][s][d]
__device__ __nv_bfloat16 g_kl[B_ * NKV_ * S_ * HD_];
__device__ __nv_bfloat16 g_vh[B_ * NKV_ * HD_ * S_];  // [b][kvh][d][s]
__device__ __nv_bfloat16 g_vl[B_ * NKV_ * HD_ * S_];

// ====================== helpers =============================================
__device__ __forceinline__ uint32_t smem_u32(const void* p) {
    uint32_t r;
    asm("{ .reg .u64 t; cvta.to.shared.u64 t, %1; cvt.u32.u64 %0, t; }"
        : "=r"(r) : "l"(p));
    return r;
}

__device__ __forceinline__ void cp16(uint32_t dst, const void* src) {
    asm volatile("cp.async.cg.shared.global [%0], [%1], 16;"
                 :: "r"(dst), "l"(src) : "memory");
}

__device__ __forceinline__ float ex2(float x) {
    float r;
    asm("ex2.approx.f32 %0, %1;" : "=f"(r) : "f"(x));
    return r;
}

__device__ __forceinline__ void mma_bf16(float c[4], uint32_t a0, uint32_t a1,
                                         uint32_t a2, uint32_t a3,
                                         uint32_t b0, uint32_t b1) {
    asm volatile(
        "mma.sync.aligned.m16n8k16.row.col.f32.bf16.bf16.f32 "
        "{%0,%1,%2,%3}, {%4,%5,%6,%7}, {%8,%9}, {%0,%1,%2,%3};"
        : "+f"(c[0]), "+f"(c[1]), "+f"(c[2]), "+f"(c[3])
        : "r"(a0), "r"(a1), "r"(a2), "r"(a3), "r"(b0), "r"(b1));
}

__device__ __forceinline__ void ldsm4(uint32_t a[4], uint32_t addr) {
    asm volatile("ldmatrix.sync.aligned.m8n8.x4.shared.b16 {%0,%1,%2,%3}, [%4];"
                 : "=r"(a[0]), "=r"(a[1]), "=r"(a[2]), "=r"(a[3]) : "r"(addr));
}

__device__ __forceinline__ void ldsm2(uint32_t a[2], uint32_t addr) {
    asm volatile("ldmatrix.sync.aligned.m8n8.x2.shared.b16 {%0,%1}, [%2];"
                 : "=r"(a[0]), "=r"(a[1]) : "r"(addr));
}

__device__ __forceinline__ void split_pack(float x0, float x1,
                                           uint32_t& hi, uint32_t& lo) {
    uint32_t h;
    asm("cvt.rn.bf16x2.f32 %0, %1, %2;" : "=r"(h) : "f"(x1), "f"(x0));
    float h0 = __uint_as_float(h << 16);
    float h1 = __uint_as_float(h & 0xFFFF0000u);
    float r0 = x0 - h0, r1 = x1 - h1;
    uint32_t l;
    asm("cvt.rn.bf16x2.f32 %0, %1, %2;" : "=r"(l) : "f"(r1), "f"(r0));
    hi = h;
    lo = l;
}

// ---------------- RoPE cos/sin table ----------------------------------------
__global__ void rope_table_kernel(float* cs, float* sn) {
    int idx = blockIdx.x * blockDim.x + threadIdx.x;
    if (idx >= S_ * 64) return;
    int s = idx >> 6;
    int p = idx & 63;
    double freq = exp(-((double)(2 * p) / (double)HD_) * log(10000.0));
    double ang = (double)s * freq;
    double sv, cv;
    sincos(ang, &sv, &cv);
    cs[idx] = (float)cv;
    sn[idx] = (float)sv;
}

// ================= HMMA split-bf16 GEMM (fused epilogues) ===================
// C[M,N] = A[M,K] @ Bt[N,K]^T (+bias). 3-stage cp.async pipeline.
// BM=128 BN=128 BK=32, 256 threads (8 warps 2x4), warp tile 64x32.
// MODE 0: fp32 out (+bias). MODE 1: Q epilogue (bias+rope+QSC+split->OH/OL).
// MODE 2: K epilogue (bias+rope+split->OH/OL).
#define HG_SA_L 18432
#define HG_SB_H 36864
#define HG_SB_L 55296
#define HG_STAGE 73728
#define HG_SMEM (3 * HG_STAGE)   // 221184

template <int MODE>
__global__ __launch_bounds__(256, 1) void hgemm_kernel(
    const __nv_bfloat16* __restrict__ Ah, const __nv_bfloat16* __restrict__ Al,
    const __nv_bfloat16* __restrict__ Bh, const __nv_bfloat16* __restrict__ Bl,
    const float* __restrict__ bias, float* __restrict__ C,
    uint32_t* __restrict__ OH, uint32_t* __restrict__ OL,
    const float* __restrict__ cs, const float* __restrict__ sn,
    int M, int N, int K) {
    extern __shared__ __align__(16) char smc[];
    uint32_t sb = smem_u32(smc);
    int tid = threadIdx.x, wid = tid >> 5, lane = tid & 31;
    int warp_m = wid >> 2, warp_n = wid & 3;
    int m0 = blockIdx.y * 128, n0 = blockIdx.x * 128;
    int g = lane >> 2, t = lane & 3;

    int r8 = lane & 7, sel = lane >> 3;
    uint32_t aoff = (uint32_t)((warp_m * 64 + (sel & 1) * 8 + r8) * 144 +
                               (sel >> 1) * 16);
    uint32_t boff = (uint32_t)((warp_n * 32 + r8) * 144 + (sel & 1) * 16);

    auto load_stage = [&](int k0, int stg) {
        uint32_t st = sb + stg * HG_STAGE;
#pragma unroll
        for (int i = 0; i < 2; i++) {
            int idx = tid + i * 256;
            int row = idx >> 2, seg = idx & 3;
            uint32_t so = row * 144 + seg * 16;
            size_t ga = (size_t)(m0 + row) * K + k0 + seg * 8;
            size_t gb = (size_t)(n0 + row) * K + k0 + seg * 8;
            cp16(st + so, Ah + ga);
            cp16(st + HG_SA_L + so, Al + ga);
            cp16(st + HG_SB_H + so, Bh + gb);
            cp16(st + HG_SB_L + so, Bl + gb);
        }
        asm volatile("cp.async.commit_group;" ::: "memory");
    };

    float acc[4][4][4];
#pragma unroll
    for (int i = 0; i < 4; i++)
#pragma unroll
        for (int j = 0; j < 4; j++)
#pragma unroll
            for (int x = 0; x < 4; x++) acc[i][j][x] = 0.0f;

    const int niter = K / 32;
    load_stage(0, 0);
    load_stage(32, 1);
    load_stage(64, 2);

    for (int it = 0; it < niter; it++) {
        int pend = niter - 1 - it;
        if (pend >= 2)
            asm volatile("cp.async.wait_group 2;" ::: "memory");
        else if (pend == 1)
            asm volatile("cp.async.wait_group 1;" ::: "memory");
        else
            asm volatile("cp.async.wait_group 0;" ::: "memory");
        __syncthreads();
        uint32_t st = sb + (it % 3) * HG_STAGE;

#pragma unroll
        for (int kc = 0; kc < 2; kc++) {
            uint32_t ah[4][4], al[4][4], bh[4][2], bl[4][2];
#pragma unroll
            for (int fm = 0; fm < 4; fm++) {
                ldsm4(ah[fm], st + aoff + fm * 2304 + kc * 32);
                ldsm4(al[fm], st + HG_SA_L + aoff + fm * 2304 + kc * 32);
            }
#pragma unroll
            for (int fn = 0; fn < 4; fn++) {
                ldsm2(bh[fn], st + HG_SB_H + boff + fn * 1152 + kc * 32);
                ldsm2(bl[fn], st + HG_SB_L + boff + fn * 1152 + kc * 32);
            }
#pragma unroll
            for (int fm = 0; fm < 4; fm++)
#pragma unroll
                for (int fn = 0; fn < 4; fn++) {
                    mma_bf16(acc[fm][fn], ah[fm][0], ah[fm][1], ah[fm][2],
                             ah[fm][3], bh[fn][0], bh[fn][1]);
                    mma_bf16(acc[fm][fn], ah[fm][0], ah[fm][1], ah[fm][2],
                             ah[fm][3], bl[fn][0], bl[fn][1]);
                    mma_bf16(acc[fm][fn], al[fm][0], al[fm][1], al[fm][2],
                             al[fm][3], bh[fn][0], bh[fn][1]);
                }
        }
        __syncthreads();
        if (it + 3 < niter) load_stage((it + 3) * 32, it % 3);
    }

    // epilogue
#pragma unroll
    for (int fm = 0; fm < 4; fm++) {
        int row0 = m0 + warp_m * 64 + fm * 16 + g;
#pragma unroll
        for (int fn = 0; fn < 4; fn++) {
            int col = n0 + warp_n * 32 + fn * 8 + 2 * t;
            float bx = 0.0f, by = 0.0f;
            if (bias) {
                float2 bb = *(const float2*)(bias + col);
                bx = bb.x;
                by = bb.y;
            }
            float vx[2] = {acc[fm][fn][0] + bx, acc[fm][fn][2] + bx};
            float vy[2] = {acc[fm][fn][1] + by, acc[fm][fn][3] + by};
            if (MODE == 0) {
                float2 v0, v1;
                v0.x = vx[0]; v0.y = vy[0];
                v1.x = vx[1]; v1.y = vy[1];
                *(float2*)(C + (size_t)row0 * N + col) = v0;
                *(float2*)(C + (size_t)(row0 + 8) * N + col) = v1;
            } else {
                int hd = col & 127;
                int hh = col >> 7;
                int p = hd >> 1;
                const int heads = (MODE == 1) ? NH_ : NKV_;
#pragma unroll
                for (int rr = 0; rr < 2; rr++) {
                    int row = row0 + rr * 8;
                    int s = row & (S_ - 1);
                    int bb_ = row >> 11;
                    float cv = cs[s * 64 + p];
                    float sv = sn[s * 64 + p];
                    float o1 = vx[rr] * cv - vy[rr] * sv;
                    float o2 = vx[rr] * sv + vy[rr] * cv;
                    if (MODE == 1) {
                        o1 *= QSC;
                        o2 *= QSC;
                    }
                    uint32_t hi, lo;
                    split_pack(o1, o2, hi, lo);
                    size_t wi = (((size_t)bb_ * heads + hh) * S_ + s) * 64 + p;
                    OH[wi] = hi;
                    OL[wi] = lo;
                }
            }
        }
    }
}

// ---------------- conversion kernels ----------------------------------------
__global__ void split_kernel(const float* __restrict__ x,
                             __nv_bfloat16* __restrict__ h,
                             __nv_bfloat16* __restrict__ l, int n4) {
    int i = blockIdx.x * blockDim.x + threadIdx.x;
    if (i >= n4) return;
    float4 v = ((const float4*)x)[i];
    uint32_t h0, l0, h1, l1;
    split_pack(v.x, v.y, h0, l0);
    split_pack(v.z, v.w, h1, l1);
    ((uint32_t*)h)[i * 2 + 0] = h0;
    ((uint32_t*)h)[i * 2 + 1] = h1;
    ((uint32_t*)l)[i * 2 + 0] = l0;
    ((uint32_t*)l)[i * 2 + 1] = l1;
}

// W [K,N] fp32 -> Th/Tl [N,K] bf16
__global__ void transpose_split_kernel(const float* __restrict__ W,
                                       __nv_bfloat16* __restrict__ Th,
                                       __nv_bfloat16* __restrict__ Tl,
                                       int K, int N) {
    __shared__ float tshm[32][33];
    int n0 = blockIdx.x * 32, k0 = blockIdx.y * 32;
    int tx = threadIdx.x, ty = threadIdx.y;  // (32,8)
#pragma unroll
    for (int i = 0; i < 32; i += 8)
        tshm[ty + i][tx] = W[(size_t)(k0 + ty + i) * N + n0 + tx];
    __syncthreads();
#pragma unroll
    for (int i = 0; i < 32; i += 8) {
        int n = n0 + ty + i, k = k0 + tx;
        float v = tshm[tx][ty + i];
        __nv_bfloat16 hb = __float2bfloat16(v);
        Th[(size_t)n * K + k] = hb;
        Tl[(size_t)n * K + k] = __float2bfloat16(v - __bfloat162float(hb));
    }
}

// V: fp32 -> bf16 hi/lo TRANSPOSED [b][kvh][d][s]
__global__ void split_vt_kernel(const float* __restrict__ v,
                                __nv_bfloat16* __restrict__ vh,
                                __nv_bfloat16* __restrict__ vl) {
    __shared__ float tshm[32][33];
    int bk = blockIdx.z;
    int b = bk >> 2, kvh = bk & 3;
    int s0 = blockIdx.x * 32, d0 = blockIdx.y * 32;
    int tx = threadIdx.x, ty = threadIdx.y;
#pragma unroll
    for (int i = 0; i < 32; i += 8)
        tshm[ty + i][tx] = v[((size_t)(b * S_ + s0 + ty + i)) * 512 + kvh * 128 + d0 + tx];
    __syncthreads();
#pragma unroll
    for (int i = 0; i < 32; i += 8) {
        float x = tshm[tx][ty + i];
        __nv_bfloat16 hb = __float2bfloat16(x);
        size_t o = ((size_t)bk * 128 + d0 + ty + i) * (size_t)S_ + s0 + tx;
        vh[o] = hb;
        vl[o] = __float2bfloat16(x - __bfloat162float(hb));
    }
}

// ---------------- Flash attention (HMMA, bf16 3-term split) -----------------
#define FL_QL 0
#define FL_QH 34816
#define FL_STG 69632
#define FL_STG_BYTES 71680
#define FL_KL 17408
#define FL_VH 34816
#define FL_VL 53248
#define FL_SMEM (FL_STG + 2 * FL_STG_BYTES)
#define NEGINF_F (__int_as_float(0xff800000))

__global__ __launch_bounds__(256, 1) void flash_hmma_kernel(
    const __nv_bfloat16* __restrict__ qhg, const __nv_bfloat16* __restrict__ qlg,
    const __nv_bfloat16* __restrict__ khg, const __nv_bfloat16* __restrict__ klg,
    const __nv_bfloat16* __restrict__ vhg, const __nv_bfloat16* __restrict__ vlg,
    uint32_t* __restrict__ outH, uint32_t* __restrict__ outL) {
    int qt = gridDim.x - 1 - blockIdx.x;
    int h = blockIdx.y;
    int b = blockIdx.z;
    int kvh = h >> 2;
    int bh = b * NH_ + h;
    int bk = b * NKV_ + kvh;

    extern __shared__ __align__(16) char sm[];
    uint32_t sbase = smem_u32(sm);
    const uint32_t* QlW = (const uint32_t*)(sm + FL_QL);
    const uint32_t* QhW = (const uint32_t*)(sm + FL_QH);

    int tid = threadIdx.x;
    int w = tid >> 5, lane = tid & 31;
    int g = lane >> 2, t = lane & 3;

    {
        const __nv_bfloat16* qh_g = qhg + ((size_t)bh * S_ + qt * 128) * 128;
        const __nv_bfloat16* ql_g = qlg + ((size_t)bh * S_ + qt * 128) * 128;
#pragma unroll
        for (int i = 0; i < 8; i++) {
            int c = tid + i * 256;
            int row = c >> 4, c16 = c & 15;
            cp16(sbase + FL_QH + row * 272 + c16 * 16, qh_g + row * 128 + c16 * 8);
            cp16(sbase + FL_QL + row * 272 + c16 * 16, ql_g + row * 128 + c16 * 8);
        }
        asm volatile("cp.async.commit_group;" ::: "memory");
    }

    const __nv_bfloat16* kh_b = khg + (size_t)bk * S_ * 128;
    const __nv_bfloat16* kl_b = klg + (size_t)bk * S_ * 128;
    const __nv_bfloat16* vh_b = vhg + (size_t)bk * 128 * S_;
    const __nv_bfloat16* vl_b = vlg + (size_t)bk * 128 * S_;

    auto load_kv = [&](int jt, int stg) {
        uint32_t sb = sbase + FL_STG + stg * FL_STG_BYTES;
#pragma unroll
        for (int i = 0; i < 4; i++) {
            int c = tid + i * 256;
            int row = c >> 4, c16 = c & 15;
            size_t go = ((size_t)(jt * 64 + row)) * 128 + c16 * 8;
            cp16(sb + row * 272 + c16 * 16, kh_b + go);
            cp16(sb + FL_KL + row * 272 + c16 * 16, kl_b + go);
        }
#pragma unroll
        for (int i = 0; i < 4; i++) {
            int c = tid + i * 256;
            int row = c >> 3, c8 = c & 7;
            size_t go = (size_t)row * S_ + jt * 64 + c8 * 8;
            cp16(sb + FL_VH + row * 144 + c8 * 16, vh_b + go);
            cp16(sb + FL_VL + row * 144 + c8 * 16, vl_b + go);
        }
        asm volatile("cp.async.commit_group;" ::: "memory");
    };

    int njt = 2 * qt + 2;
    load_kv(0, 0);
    load_kv(1, 1);
    asm volatile("cp.async.wait_group 2;" ::: "memory");
    __syncthreads();

    float o_[16][4];
#pragma unroll
    for (int n = 0; n < 16; n++)
#pragma unroll
        for (int j = 0; j < 4; j++) o_[n][j] = 0.0f;
    float m0 = NEGINF_F, m1 = NEGINF_F, l0 = 0.0f, l1 = 0.0f;

    for (int jt = 0; jt < njt; jt++) {
        if (jt < njt - 1)
            asm volatile("cp.async.wait_group 1;" ::: "memory");
        else
            asm volatile("cp.async.wait_group 0;" ::: "memory");
        __syncthreads();

        const uint32_t* KhW = (const uint32_t*)(sm + FL_STG + (jt & 1) * FL_STG_BYTES);
        const uint32_t* KlW = KhW + FL_KL / 4;
        const uint32_t* VhW = KhW + FL_VH / 4;
        const uint32_t* VlW = KhW + FL_VL / 4;

        float s[8][4];
#pragma unroll
        for (int j = 0; j < 8; j++)
#pragma unroll
            for (int x = 0; x < 4; x++) s[j][x] = 0.0f;

        for (int kk = 0; kk < 8; kk++) {
            int qi = (w * 16 + g) * 68 + kk * 8 + t;
            uint32_t qh0 = QhW[qi], qh1 = QhW[qi + 8 * 68];
            uint32_t qh2 = QhW[qi + 4], qh3 = QhW[qi + 8 * 68 + 4];
            uint32_t ql0 = QlW[qi], ql1 = QlW[qi + 8 * 68];
            uint32_t ql2 = QlW[qi + 4], ql3 = QlW[qi + 8 * 68 + 4];
#pragma unroll
            for (int j = 0; j < 8; j++) {
                int ki = (8 * j + g) * 68 + kk * 8 + t;
                uint32_t kb0 = KhW[ki], kb1 = KhW[ki + 4];
                uint32_t lb0 = KlW[ki], lb1 = KlW[ki + 4];
                mma_bf16(s[j], qh0, qh1, qh2, qh3, kb0, kb1);
                mma_bf16(s[j], qh0, qh1, qh2, qh3, lb0, lb1);
                mma_bf16(s[j], ql0, ql1, ql2, ql3, kb0, kb1);
            }
        }

        if (jt * 64 + 63 > qt * 128 + w * 16) {
            int row0 = qt * 128 + w * 16 + g;
            int row1 = row0 + 8;
#pragma unroll
            for (int j = 0; j < 8; j++) {
                int col = jt * 64 + 8 * j + 2 * t;
                if (col > row0) s[j][0] = NEGINF_F;
                if (col + 1 > row0) s[j][1] = NEGINF_F;
                if (col > row1) s[j][2] = NEGINF_F;
                if (col + 1 > row1) s[j][3] = NEGINF_F;
            }
        }

        float mx0 = NEGINF_F, mx1 = NEGINF_F;
#pragma unroll
        for (int j = 0; j < 8; j++) {
            mx0 = fmaxf(mx0, fmaxf(s[j][0], s[j][1]));
            mx1 = fmaxf(mx1, fmaxf(s[j][2], s[j][3]));
        }
        mx0 = fmaxf(mx0, __shfl_xor_sync(0xffffffff, mx0, 1));
        mx0 = fmaxf(mx0, __shfl_xor_sync(0xffffffff, mx0, 2));
        mx1 = fmaxf(mx1, __shfl_xor_sync(0xffffffff, mx1, 1));
        mx1 = fmaxf(mx1, __shfl_xor_sync(0xffffffff, mx1, 2));
        float mn0 = fmaxf(m0, mx0), mn1 = fmaxf(m1, mx1);
        float a0 = ex2(m0 - mn0), a1 = ex2(m1 - mn1);
        m0 = mn0;
        m1 = mn1;
        float sum0 = 0.0f, sum1 = 0.0f;
#pragma unroll
        for (int j = 0; j < 8; j++) {
            s[j][0] = ex2(s[j][0] - mn0);
            s[j][1] = ex2(s[j][1] - mn0);
            s[j][2] = ex2(s[j][2] - mn1);
            s[j][3] = ex2(s[j][3] - mn1);
            sum0 += s[j][0] + s[j][1];
            sum1 += s[j][2] + s[j][3];
        }
        sum0 += __shfl_xor_sync(0xffffffff, sum0, 1);
        sum0 += __shfl_xor_sync(0xffffffff, sum0, 2);
        sum1 += __shfl_xor_sync(0xffffffff, sum1, 1);
        sum1 += __shfl_xor_sync(0xffffffff, sum1, 2);
        l0 = l0 * a0 + sum0;
        l1 = l1 * a1 + sum1;
#pragma unroll
        for (int n = 0; n < 16; n++) {
            o_[n][0] *= a0;
            o_[n][1] *= a0;
            o_[n][2] *= a1;
            o_[n][3] *= a1;
        }

#pragma unroll
        for (int kk = 0; kk < 4; kk++) {
            uint32_t pa0, pa1, pa2, pa3, la0, la1, la2, la3;
            split_pack(s[2 * kk][0], s[2 * kk][1], pa0, la0);
            split_pack(s[2 * kk][2], s[2 * kk][3], pa1, la1);
            split_pack(s[2 * kk + 1][0], s[2 * kk + 1][1], pa2, la2);
            split_pack(s[2 * kk + 1][2], s[2 * kk + 1][3], pa3, la3);
#pragma unroll
            for (int n = 0; n < 16; n++) {
                int vi = (8 * n + g) * 36 + kk * 8 + t;
                uint32_t vb0 = VhW[vi], vb1 = VhW[vi + 4];
                uint32_t wb0 = VlW[vi], wb1 = VlW[vi + 4];
                mma_bf16(o_[n], pa0, pa1, pa2, pa3, vb0, vb1);
                mma_bf16(o_[n], pa0, pa1, pa2, pa3, wb0, wb1);
                mma_bf16(o_[n], la0, la1, la2, la3, vb0, vb1);
            }
        }

        __syncthreads();
        if (jt + 2 < njt) load_kv(jt + 2, jt & 1);
    }

    // epilogue: normalize + bf16 split, write at_h/at_l directly
    float inv0 = 1.0f / l0, inv1 = 1.0f / l1;
    int row0 = qt * 128 + w * 16 + g;
    int row1 = row0 + 8;
#pragma unroll
    for (int n = 0; n < 16; n++) {
        int col = h * 128 + 8 * n + 2 * t;
        uint32_t hi0, lo0, hi1, lo1;
        split_pack(o_[n][0] * inv0, o_[n][1] * inv0, hi0, lo0);
        split_pack(o_[n][2] * inv1, o_[n][3] * inv1, hi1, lo1);
        size_t w0 = ((size_t)(b * S_ + row0) * 2048 + col) >> 1;
        size_t w1 = ((size_t)(b * S_ + row1) * 2048 + col) >> 1;
        outH[w0] = hi0;
        outL[w0] = lo0;
        outH[w1] = hi1;
        outL[w1] = lo1;
    }
}

// ---------------- launch ----------------------------------------------------
extern "C" void kernel_launch(void* const* d_in, const int* in_sizes, int n_in,
                              void* d_out, int out_size) {
    const float* hs  = (const float*)d_in[0];
    const float* q_w = (const float*)d_in[1];
    const float* q_b = (const float*)d_in[2];
    const float* k_w = (const float*)d_in[3];
    const float* k_b = (const float*)d_in[4];
    const float* v_w = (const float*)d_in[5];
    const float* v_b = (const float*)d_in[6];
    const float* o_w = (const float*)d_in[7];
    float* out = (float*)d_out;

    float *vp, *cp, *sp;
    cudaGetSymbolAddress((void**)&vp, g_v);
    cudaGetSymbolAddress((void**)&cp, g_cos);
    cudaGetSymbolAddress((void**)&sp, g_sin);

    __nv_bfloat16 *hsh, *hsl, *ath, *atl, *qwh, *qwl, *kwh, *kwl, *vwh, *vwl, *owh, *owl;
    cudaGetSymbolAddress((void**)&hsh, g_hs_h);
    cudaGetSymbolAddress((void**)&hsl, g_hs_l);
    cudaGetSymbolAddress((void**)&ath, g_at_h);
    cudaGetSymbolAddress((void**)&atl, g_at_l);
    cudaGetSymbolAddress((void**)&qwh, g_qw_h);
    cudaGetSymbolAddress((void**)&qwl, g_qw_l);
    cudaGetSymbolAddress((void**)&kwh, g_kw_h);
    cudaGetSymbolAddress((void**)&kwl, g_kw_l);
    cudaGetSymbolAddress((void**)&vwh, g_vw_h);
    cudaGetSymbolAddress((void**)&vwl, g_vw_l);
    cudaGetSymbolAddress((void**)&owh, g_ow_h);
    cudaGetSymbolAddress((void**)&owl, g_ow_l);

    __nv_bfloat16 *qh, *ql, *kh, *kl, *vh, *vl;
    cudaGetSymbolAddress((void**)&qh, g_qh);
    cudaGetSymbolAddress((void**)&ql, g_ql);
    cudaGetSymbolAddress((void**)&kh, g_kh);
    cudaGetSymbolAddress((void**)&kl, g_kl);
    cudaGetSymbolAddress((void**)&vh, g_vh);
    cudaGetSymbolAddress((void**)&vl, g_vl);

    cudaFuncSetAttribute(hgemm_kernel<0>,
                         cudaFuncAttributeMaxDynamicSharedMemorySize, HG_SMEM);
    cudaFuncSetAttribute(hgemm_kernel<1>,
                         cudaFuncAttributeMaxDynamicSharedMemorySize, HG_SMEM);
    cudaFuncSetAttribute(hgemm_kernel<2>,
                         cudaFuncAttributeMaxDynamicSharedMemorySize, HG_SMEM);
    cudaFuncSetAttribute(flash_hmma_kernel,
                         cudaFuncAttributeMaxDynamicSharedMemorySize, FL_SMEM);

    // RoPE table (needed by GEMM epilogues)
    rope_table_kernel<<<(S_ * 64 + 255) / 256, 256>>>(cp, sp);

    // Convert operands to split bf16
    int n4_hs = (ROWS_ * HID_) / 4;
    split_kernel<<<(n4_hs + 255) / 256, 256>>>(hs, hsh, hsl, n4_hs);
    dim3 tb(32, 8);
    transpose_split_kernel<<<dim3(2048 / 32, 2048 / 32), tb>>>(q_w, qwh, qwl, 2048, 2048);
    transpose_split_kernel<<<dim3(512 / 32, 2048 / 32), tb>>>(k_w, kwh, kwl, 2048, 512);
    transpose_split_kernel<<<dim3(512 / 32, 2048 / 32), tb>>>(v_w, vwh, vwl, 2048, 512);
    transpose_split_kernel<<<dim3(2048 / 32, 2048 / 32), tb>>>(o_w, owh, owl, 2048, 2048);

    // QKV projections with fused epilogues
    dim3 gq(2048 / 128, ROWS_ / 128);   // (16, 32)
    dim3 gkv(512 / 128, ROWS_ / 128);   // (4, 32)
    hgemm_kernel<1><<<gq, 256, HG_SMEM>>>(hsh, hsl, qwh, qwl, q_b, nullptr,
                                          (uint32_t*)qh, (uint32_t*)ql, cp, sp,
                                          ROWS_, NH_ * HD_, HID_);
    hgemm_kernel<2><<<gkv, 256, HG_SMEM>>>(hsh, hsl, kwh, kwl, k_b, nullptr,
                                           (uint32_t*)kh, (uint32_t*)kl, cp, sp,
                                           ROWS_, NKV_ * HD_, HID_);
    hgemm_kernel<0><<<gkv, 256, HG_SMEM>>>(hsh, hsl, vwh, vwl, v_b, vp,
                                           nullptr, nullptr, nullptr, nullptr,
                                           ROWS_, NKV_ * HD_, HID_);

    // V transpose+split
    dim3 tv(32, 8);
    split_vt_kernel<<<dim3(S_ / 32, HD_ / 32, B_ * NKV_), tv>>>(vp, vh, vl);

    // Flash attention (writes at_h/at_l)
    dim3 gf(S_ / 128, NH_, B_);
    flash_hmma_kernel<<<gf, 256, FL_SMEM>>>(qh, ql, kh, kl, vh, vl,
                                            (uint32_t*)ath, (uint32_t*)atl);

    // Output projection (fp32 out, no bias)
    hgemm_kernel<0><<<gq, 256, HG_SMEM>>>(ath, atl, owh, owl, nullptr, out,
                                          nullptr, nullptr, nullptr, nullptr,
                                          ROWS_, HID_, NH_ * HD_);
}